// round 13
// baseline (speedup 1.0000x reference)
#include <cuda_runtime.h>
#include <cuda_fp16.h>
#include <math.h>
#include <stdint.h>

#define Bsz 512
#define Dd  1024
#define Hh  2048
#define MAXS 8

#define OFF_ENC    0
#define OFF_NS     (Bsz*Dd)
#define OFF_COMMIT (Bsz*Dd + Bsz*Hh*5)
#define OFF_DRIFT  (OFF_COMMIT + 1)

// ===================== device scratch =====================
__device__ float g_drift[Bsz*Dd];
__device__ float g_dp0[Bsz*Dd];
__device__ float g_dp1[Bsz*Dd];
__device__ float g_li[Bsz*Hh];
__device__ float g_k [Bsz*Hh];
__device__ float g_v [Bsz*Hh];
__device__ float g_r [Bsz*Hh];
__device__ float g_r2[Bsz*Hh];
__device__ float g_tm[Bsz*Hh];
__device__ float g_cm[Bsz*Hh];
__device__ float g_sxx[Bsz*Hh];
__device__ float g_saa[Bsz*Hh];
__device__ float g_sbb[Bsz*Hh];
__device__ float g_spp[Bsz*Hh];
__device__ float g_scc[Bsz*Hh];
__device__ float g_part[256][2];
__device__ float g_csum, g_cnt;
__device__ int   g_done;
__device__ int   g_rcount;

// fp16 split A buffers [512 x 2048]
__device__ __half g_A0h[Bsz*Hh],  g_A0l[Bsz*Hh];
__device__ __half g_Axkh[Bsz*Hh], g_Axkl[Bsz*Hh];
__device__ __half g_Axvh[Bsz*Hh], g_Axvl[Bsz*Hh];
__device__ __half g_Axrh[Bsz*Hh], g_Axrl[Bsz*Hh];
__device__ __half g_Axk2h[Bsz*Hh],g_Axk2l[Bsz*Hh];
__device__ __half g_Axr2h[Bsz*Hh],g_Axr2l[Bsz*Hh];
__device__ __half g_Aah[Bsz*Hh],  g_Aal[Bsz*Hh];
__device__ __half g_Akkh[Bsz*Hh], g_Akkl[Bsz*Hh];

// transposed + split weights [N, 2048] fp16
__device__ __half g_WinTh[Hh*2048],  g_WinTl[Hh*2048];
__device__ __half g_WkTh [Hh*Hh],    g_WkTl [Hh*Hh];
__device__ __half g_WvTh [Hh*Hh],    g_WvTl [Hh*Hh];
__device__ __half g_WrTh [Hh*Hh],    g_WrTl [Hh*Hh];
__device__ __half g_WoTh [Hh*Hh],    g_WoTl [Hh*Hh];
__device__ __half g_Wk2Th[Hh*Hh],    g_Wk2Tl[Hh*Hh];
__device__ __half g_Wv2Th[Hh*Hh],    g_Wv2Tl[Hh*Hh];
__device__ __half g_Wr2Th[Hh*Hh],    g_Wr2Tl[Hh*Hh];
__device__ __half g_WdTh [Dd*Hh],    g_WdTl [Dd*Hh];
__device__ __half g_WoutTh[Dd*Hh],   g_WoutTl[Dd*Hh];

__device__ __forceinline__ float clip50(float x){ return fminf(fmaxf(x, -50.f), 50.f); }
__device__ __forceinline__ void split_store(float v, __half* H, __half* L, size_t i){
    __half h = __float2half_rn(v);
    H[i] = h;
    L[i] = __float2half_rn(v - __half2float(h));
}
__device__ __forceinline__ void split2(float v0, float v1, __half* H, __half* L, size_t i){
    __half h0 = __float2half_rn(v0), h1 = __float2half_rn(v1);
    *(__half2*)(H + i) = __halves2half2(h0, h1);
    *(__half2*)(L + i) = __halves2half2(__float2half_rn(v0 - __half2float(h0)),
                                        __float2half_rn(v1 - __half2float(h1)));
}

// ===================== PTX primitives (compute_103-generic) =====================
__device__ __forceinline__ uint32_t smem_u32(const void* p){
    uint32_t a;
    asm("{ .reg .u64 t; cvta.to.shared.u64 t, %1; cvt.u32.u64 %0, t; }" : "=r"(a) : "l"(p));
    return a;
}
__device__ __forceinline__ void cp16(uint32_t s, const void* g){
    asm volatile("cp.async.cg.shared.global [%0], [%1], 16;" :: "r"(s), "l"(g));
}
#define CP_COMMIT() asm volatile("cp.async.commit_group;" ::: "memory")
#define CP_WAIT(n)  asm volatile("cp.async.wait_group %0;" :: "n"(n) : "memory")

__device__ __forceinline__ void ldm4(uint32_t* r, uint32_t a){
    asm volatile("ldmatrix.sync.aligned.m8n8.x4.shared.b16 {%0,%1,%2,%3}, [%4];"
        : "=r"(r[0]), "=r"(r[1]), "=r"(r[2]), "=r"(r[3]) : "r"(a));
}
__device__ __forceinline__ void mma16816(float* d, const uint32_t* a, const uint32_t* b){
    asm volatile("mma.sync.aligned.m16n8k16.row.col.f32.f16.f16.f32 "
        "{%0,%1,%2,%3}, {%4,%5,%6,%7}, {%8,%9}, {%0,%1,%2,%3};"
        : "+f"(d[0]), "+f"(d[1]), "+f"(d[2]), "+f"(d[3])
        : "r"(a[0]), "r"(a[1]), "r"(a[2]), "r"(a[3]), "r"(b[0]), "r"(b[1]));
}

// ===================== weight transpose + split (once per launch) =====================
struct TSE { const float* s; __half *dh, *dl; int nc; };
struct TSP { TSE w[10]; };

__global__ void k_transsplit(TSP p)
{
    TSE e = p.w[blockIdx.z];
    int n0 = blockIdx.y * 32;
    if (n0 >= e.nc) return;
    int k0 = blockIdx.x * 32;
    __shared__ float t[32][33];
    int tx = threadIdx.x, ty = threadIdx.y;
#pragma unroll
    for (int j = 0; j < 4; j++)
        t[ty + j*8][tx] = e.s[(size_t)(k0 + ty + j*8) * e.nc + n0 + tx];
    __syncthreads();
#pragma unroll
    for (int j = 0; j < 4; j++) {
        int n = n0 + ty + j*8, k = k0 + tx;
        float v = t[tx][ty + j*8];
        __half h = __float2half_rn(v);
        e.dh[(size_t)n * 2048 + k] = h;
        e.dl[(size_t)n * 2048 + k] = __float2half_rn(v - __half2float(h));
    }
}

// ===================== HMMA GEMM =====================
struct TZ {
    const __half *Ahi, *Alo, *Bhi, *Blo;
    float* C;
    __half *Chi, *Clo;
    int epi; // 0 plain, 1 clip+bias, 2 sigmoid, 3 relu^2->split, 4 tanh,
             // 5 enc+acc+bias, 6 fused li+mix (shadow), 7 fused li+mix (commit lstate)
    int tb, te;  // chunk range (K64 chunks); full = 0..32
    int amode;   // 0: cp.async split planes; 1: A = split(tm + r2*cm) computed in-kernel
};
struct TGP {
    TZ z[5];
    const float* bias;
    const float* enc;
    const float *mixk, *mixv, *mixr, *mixk2, *mixr2, *lst;
    int N, gated;
};

#define BM 128
#define BN 64
#define BKh 64
#define NT 128          /* threads per CTA */
#define STG 2
#define APL_B 16384     /* one A plane per stage */
#define BPL_B 8192      /* one B plane per stage */
#define STG_BYTES (2*APL_B + 2*BPL_B)   /* Ahi, Alo, Bhi, Blo = 48KB */
#define SMEM_TOT (STG*STG_BYTES)        /* 96KB -> 2 CTA/SM */

__global__ __launch_bounds__(NT, 2) void k_mma(TGP p)
{
    if (p.gated && g_done) return;
    extern __shared__ __align__(128) char sm[];
    const uint32_t smb = smem_u32(sm);
    const TZ gz = p.z[blockIdx.z];
    const int tid = threadIdx.x, l = tid & 31, wid = tid >> 5;
    const int m0 = blockIdx.y * BM, n0 = blockIdx.x * BN;
    const int wm = (wid >> 1) * 64, wn = (wid & 1) * 32;  // 2x2 warp grid, 64x32 warp tile

    float acc[4][4][4];
#pragma unroll
    for (int i = 0; i < 4; i++)
#pragma unroll
        for (int j = 0; j < 4; j++)
#pragma unroll
            for (int q = 0; q < 4; q++) acc[i][j][q] = 0.f;

    // cp.async mapping (128 threads): per A plane 1024 vec (8/thread), per B plane 512 vec (4/thread)
    int a_r[8], a_c[8]; uint32_t a_so[8];
#pragma unroll
    for (int i = 0; i < 8; i++) {
        int v = tid + i * NT;
        a_r[i] = v >> 3; a_c[i] = v & 7;
        a_so[i] = (uint32_t)(a_r[i] * 128 + ((a_c[i] ^ (a_r[i] & 7)) << 4));
    }
    int b_r[4], b_c[4]; uint32_t b_so[4];
#pragma unroll
    for (int i = 0; i < 4; i++) {
        int v = tid + i * NT;
        b_r[i] = v >> 3; b_c[i] = v & 7;
        b_so[i] = (uint32_t)(b_r[i] * 128 + ((b_c[i] ^ (b_r[i] & 7)) << 4));
    }

    auto load_stage = [&](int stage, int t){
        int kc = t * BKh;
        uint32_t base = smb + stage * STG_BYTES;
        char* cbase = sm + stage * STG_BYTES;
        if (gz.amode) {
            // A tile = split(tm + r2*cm), computed in registers, stored via STS
#pragma unroll
            for (int i = 0; i < 8; i++) {
                size_t gix = (size_t)(m0 + a_r[i]) * 2048 + kc + a_c[i] * 8;
                __half hh[8], ll[8];
#pragma unroll
                for (int e = 0; e < 8; e += 4) {
                    float4 tmv = *(const float4*)(g_tm + gix + e);
                    float4 rv  = *(const float4*)(g_r2 + gix + e);
                    float4 cv  = *(const float4*)(g_cm + gix + e);
                    float vv[4] = {tmv.x + rv.x*cv.x, tmv.y + rv.y*cv.y,
                                   tmv.z + rv.z*cv.z, tmv.w + rv.w*cv.w};
#pragma unroll
                    for (int q = 0; q < 4; q++) {
                        __half h = __float2half_rn(vv[q]);
                        hh[e+q] = h;
                        ll[e+q] = __float2half_rn(vv[q] - __half2float(h));
                    }
                }
                *(uint4*)(cbase + a_so[i])         = *(uint4*)hh;
                *(uint4*)(cbase + APL_B + a_so[i]) = *(uint4*)ll;
            }
        } else {
#pragma unroll
            for (int i = 0; i < 8; i++)
                cp16(base + a_so[i], gz.Ahi + (size_t)(m0 + a_r[i]) * 2048 + kc + a_c[i] * 8);
#pragma unroll
            for (int i = 0; i < 8; i++)
                cp16(base + APL_B + a_so[i], gz.Alo + (size_t)(m0 + a_r[i]) * 2048 + kc + a_c[i] * 8);
        }
#pragma unroll
        for (int i = 0; i < 4; i++)
            cp16(base + 2*APL_B + b_so[i], gz.Bhi + (size_t)(n0 + b_r[i]) * 2048 + kc + b_c[i] * 8);
#pragma unroll
        for (int i = 0; i < 4; i++)
            cp16(base + 2*APL_B + BPL_B + b_so[i], gz.Blo + (size_t)(n0 + b_r[i]) * 2048 + kc + b_c[i] * 8);
        CP_COMMIT();
    };

    // ldmatrix lane-constant pieces
    const int ar  = wm + (l & 15);       // + mi*16   (A m16k16 x4)
    const int ahi = (l >> 4) & 1;
    const int bn4 = wn + (l & 7) + ((l >> 4) & 1) * 8;  // B n16k16 x4 (two n8 tiles)
    const int bhi = (l >> 3) & 1;

    load_stage(gz.tb & 1, gz.tb);

    // Single-sync pipeline: wait(chunk t ready) -> sync -> issue loads t+1 -> compute t.
    for (int t = gz.tb; t < gz.te; t++) {
        CP_WAIT(0);
        __syncthreads();
        if (t + 1 < gz.te) load_stage((t + 1) & 1, t + 1);

        uint32_t base = smb + (t & 1) * STG_BYTES;
        uint32_t Ah = base, Al = base + APL_B;
        uint32_t Bh = base + 2*APL_B, Bl = base + 2*APL_B + BPL_B;

        // fragment double-buffering across kk: load kk+1 frags while computing kk
        uint32_t ah[2][4][4], al[2][4][4], bh[2][2][4], bl[2][2][4];
        auto ldfr = [&](int buf, int kk){
#pragma unroll
            for (int mi = 0; mi < 4; mi++) {
                int r = ar + mi * 16, c = kk * 2 + ahi;
                uint32_t off = (uint32_t)(r * 128 + ((c ^ (r & 7)) << 4));
                ldm4(ah[buf][mi], Ah + off);
                ldm4(al[buf][mi], Al + off);
            }
#pragma unroll
            for (int g = 0; g < 2; g++) {
                int n = bn4 + g * 16, c = kk * 2 + bhi;
                uint32_t off = (uint32_t)(n * 128 + ((c ^ (n & 7)) << 4));
                ldm4(bh[buf][g], Bh + off);
                ldm4(bl[buf][g], Bl + off);
            }
        };
        ldfr(0, 0);
#pragma unroll
        for (int kk = 0; kk < 4; kk++) {
            int cur = kk & 1, nxt = cur ^ 1;
            if (kk < 3) ldfr(nxt, kk + 1);
            // pass 1: Ahi * Bhi
#pragma unroll
            for (int mi = 0; mi < 4; mi++)
#pragma unroll
                for (int ni = 0; ni < 4; ni++)
                    mma16816(acc[mi][ni], ah[cur][mi], &bh[cur][ni >> 1][(ni & 1) * 2]);
            // pass 2: Ahi * Blo
#pragma unroll
            for (int mi = 0; mi < 4; mi++)
#pragma unroll
                for (int ni = 0; ni < 4; ni++)
                    mma16816(acc[mi][ni], ah[cur][mi], &bl[cur][ni >> 1][(ni & 1) * 2]);
            // pass 3: Alo * Bhi
#pragma unroll
            for (int mi = 0; mi < 4; mi++)
#pragma unroll
                for (int ni = 0; ni < 4; ni++)
                    mma16816(acc[mi][ni], al[cur][mi], &bh[cur][ni >> 1][(ni & 1) * 2]);
        }
    }

    // ---- epilogue ----
    const int rl = l >> 2, cl = (l & 3) * 2;
    const int N = p.N;
#pragma unroll
    for (int mi = 0; mi < 4; mi++) {
#pragma unroll
        for (int ni = 0; ni < 4; ni++) {
            float* a = acc[mi][ni];
#pragma unroll
            for (int h = 0; h < 2; h++) {
                int r = m0 + wm + mi * 16 + h * 8 + rl;
                int c = n0 + wn + ni * 8 + cl;
                float v0 = a[2*h], v1 = a[2*h + 1];
                size_t i0 = (size_t)r * N + c;

                if (gz.epi >= 6) {
                    float li0 = clip50(v0 + p.bias[c]);
                    float li1 = clip50(v1 + p.bias[c + 1]);
                    *(float2*)(gz.C + i0) = make_float2(li0, li1);
                    float xx0, xx1, cc0, cc1;
                    if (gz.epi == 7) {
                        const float* s = p.lst + i0 * 5;
                        xx0 = s[0]; cc0 = s[4]; xx1 = s[5]; cc1 = s[9];
                    } else {
                        xx0 = g_sxx[i0]; xx1 = g_sxx[i0 + 1];
                        cc0 = g_scc[i0]; cc1 = g_scc[i0 + 1];
                    }
                    float a0, a1;
                    a0 = p.mixk[c];  a1 = p.mixk[c+1];
                    split2(li0*a0 + xx0*(1.f-a0), li1*a1 + xx1*(1.f-a1), g_Axkh,  g_Axkl,  i0);
                    a0 = p.mixv[c];  a1 = p.mixv[c+1];
                    split2(li0*a0 + xx0*(1.f-a0), li1*a1 + xx1*(1.f-a1), g_Axvh,  g_Axvl,  i0);
                    a0 = p.mixr[c];  a1 = p.mixr[c+1];
                    split2(li0*a0 + xx0*(1.f-a0), li1*a1 + xx1*(1.f-a1), g_Axrh,  g_Axrl,  i0);
                    a0 = p.mixk2[c]; a1 = p.mixk2[c+1];
                    split2(li0*a0 + cc0*(1.f-a0), li1*a1 + cc1*(1.f-a1), g_Axk2h, g_Axk2l, i0);
                    a0 = p.mixr2[c]; a1 = p.mixr2[c+1];
                    split2(li0*a0 + cc0*(1.f-a0), li1*a1 + cc1*(1.f-a1), g_Axr2h, g_Axr2l, i0);
                } else if (gz.epi == 3) {
                    float t0 = fmaxf(v0, 0.f); v0 = t0 * t0;
                    float t1 = fmaxf(v1, 0.f); v1 = t1 * t1;
                    split2(v0, v1, gz.Chi, gz.Clo, i0);
                } else {
                    switch (gz.epi) {
                    case 1:
                        v0 = clip50(v0 + p.bias[c]);
                        v1 = clip50(v1 + p.bias[c + 1]);
                        break;
                    case 2:
                        v0 = 1.f / (1.f + expf(-v0));
                        v1 = 1.f / (1.f + expf(-v1));
                        break;
                    case 4:
                        v0 = tanhf(v0); v1 = tanhf(v1);
                        break;
                    case 5:
                        v0 += p.enc[i0]     + p.bias[c];
                        v1 += p.enc[i0 + 1] + p.bias[c + 1];
                        break;
                    default: break;
                    }
                    *(float2*)(gz.C + i0) = make_float2(v0, v1);
                }
            }
        }
    }
}

// ===================== elementwise kernels =====================
__global__ void k_init(const float* enc, const float* sc,
                       const float* lstate, const float* idrift)
{
    int i = blockIdx.x * blockDim.x + threadIdx.x;
    if (i < Bsz * Hh) {
        const float* s = lstate + (size_t)i * 5;
        g_sxx[i] = s[0]; g_saa[i] = s[1]; g_sbb[i] = s[2]; g_spp[i] = s[3]; g_scc[i] = s[4];
    }
    if (i < Bsz * Dd) {
        g_drift[i] = idrift[i];
        int m = i >> 10, col = i & 1023;
        size_t a0 = (size_t)m * 2048 + col;
        split_store(enc[i], g_A0h, g_A0l, a0);
        split_store(sc[i] + idrift[i], g_A0h, g_A0l, a0 + 1024);
    }
    if (i == 0) { g_csum = 0.f; g_cnt = 0.f; g_done = 0; g_rcount = 0; }
}

__global__ void k_cell(const float* tf, const float* td,
                       const float* lstate_in, float* ns_out, int gated)
{
    if (gated && g_done) return;
    int i = blockIdx.x * blockDim.x + threadIdx.x;
    int h = i & (Hh - 1);
    float kx = g_k[i], v = g_v[i], r = g_r[i], li = g_li[i];
    float aa, bb, pp;
    if (lstate_in) {
        const float* s = lstate_in + (size_t)i * 5;
        aa = s[1]; bb = s[2]; pp = s[3];
    } else {
        aa = g_saa[i]; bb = g_sbb[i]; pp = g_spp[i];
    }
    float ww = tf[h] + kx;
    float q  = fmaxf(pp, ww);
    float e1 = expf(pp - q), e2 = expf(ww - q);
    float wkv = (e1 * aa + e2 * v) / (e1 * bb + e2);
    split_store(r * wkv, g_Aah, g_Aal, i);

    float ww2 = pp - expf(td[h]);
    float q2  = fmaxf(ww2, kx);
    float e1b = expf(ww2 - q2), e2b = expf(kx - q2);
    float naa = clip50(e1b * aa + e2b * v);
    float nbb = clip50(e1b * bb + e2b);
    float npp = clip50(q2);
    float nxx = clip50(li);
    if (ns_out) {
        float* o = ns_out + (size_t)i * 5;
        o[0] = nxx; o[1] = naa; o[2] = nbb; o[3] = npp; o[4] = nxx;
    } else {
        g_sxx[i] = nxx; g_saa[i] = naa; g_sbb[i] = nbb; g_spp[i] = npp; g_scc[i] = nxx;
    }
}

// drift update (split-K partials + tanh) + A0 refresh + partials + fused final reduce
__global__ void k_reduce(const float* sc)
{
    if (g_done) return;
    __shared__ float sA[256], sB[256];
    __shared__ int isLast;
    int t = threadIdx.x;
    size_t base = (size_t)blockIdx.x * 2048 + t;
    float sa = 0.f, sn = 0.f;
#pragma unroll
    for (int j = 0; j < 8; j++) {
        size_t i = base + (size_t)j * 256;
        float d  = tanhf(g_dp0[i] + g_dp1[i]);
        float nd = fminf(fmaxf(g_drift[i] + d, -5.f), 5.f);
        g_drift[i] = nd;
        int m = (int)(i >> 10), col = (int)(i & 1023);
        split_store(sc[i] + nd, g_A0h, g_A0l, (size_t)m * 2048 + 1024 + col);
        sa += fabsf(d);
        sn += nd * nd;
    }
    sA[t] = sa; sB[t] = sn;
    __syncthreads();
    for (int s = 128; s > 0; s >>= 1) {
        if (t < s) { sA[t] += sA[t + s]; sB[t] += sB[t + s]; }
        __syncthreads();
    }
    if (t == 0) {
        g_part[blockIdx.x][0] = sA[0];
        g_part[blockIdx.x][1] = sB[0];
        __threadfence();
        int c = atomicAdd(&g_rcount, 1);
        isLast = (c == 255);
    }
    __syncthreads();
    if (!isLast) return;

    // last block: final reduce (deterministic — fixed partials, fixed order)
    sA[t] = g_part[t][0]; sB[t] = g_part[t][1];
    __syncthreads();
    for (int s = 128; s > 0; s >>= 1) {
        if (t < s) { sA[t] += sA[t + s]; sB[t] += sB[t + s]; }
        __syncthreads();
    }
    if (t == 0) {
        float hinge = fminf(fmaxf(sB[0] / (float)Bsz - 0.1f, 0.f), 100.f);
        g_csum += hinge;
        g_cnt  += 1.f;
        if (sA[0] * (1.f / (float)(Bsz * Dd)) < 0.01f) g_done = 1;
        g_rcount = 0;
    }
}

__global__ void k_final(float* out)
{
    int i = blockIdx.x * blockDim.x + threadIdx.x;
    if (i < Bsz * Dd) out[OFF_DRIFT + i] = g_drift[i];
    if (i == 0) out[OFF_COMMIT] = g_csum / fmaxf(g_cnt, 1.f);
}

// ===================== host =====================
#define SYM(p, s) cudaGetSymbolAddress((void**)&(p), s)

extern "C" void kernel_launch(void* const* d_in, const int* in_sizes, int n_in,
                              void* d_out, int out_size)
{
    (void)in_sizes; (void)n_in; (void)out_size;
    const float* enc    = (const float*)d_in[0];
    const float* sc     = (const float*)d_in[1];
    const float* lstate = (const float*)d_in[2];
    const float* idrift = (const float*)d_in[3];
    const float* Win    = (const float*)d_in[4];
    const float* b_in   = (const float*)d_in[5];
    const float* Wdrift = (const float*)d_in[6];
    const float* Wout   = (const float*)d_in[7];
    const float* b_out  = (const float*)d_in[8];
    const float* mix_k  = (const float*)d_in[9];
    const float* mix_v  = (const float*)d_in[10];
    const float* mix_r  = (const float*)d_in[11];
    const float* mix_k2 = (const float*)d_in[12];
    const float* mix_r2 = (const float*)d_in[13];
    const float* tdec   = (const float*)d_in[14];
    const float* tfirst = (const float*)d_in[15];
    const float* Wk  = (const float*)d_in[16];
    const float* Wv  = (const float*)d_in[17];
    const float* Wr  = (const float*)d_in[18];
    const float* Wo  = (const float*)d_in[19];
    const float* Wk2 = (const float*)d_in[20];
    const float* Wv2 = (const float*)d_in[21];
    const float* Wr2 = (const float*)d_in[22];
    float* out = (float*)d_out;

    cudaFuncSetAttribute(k_mma, cudaFuncAttributeMaxDynamicSharedMemorySize, SMEM_TOT);

    float *p_li, *p_k, *p_v, *p_r, *p_r2, *p_tm, *p_cm, *p_dp0, *p_dp1;
    SYM(p_li, g_li); SYM(p_k, g_k); SYM(p_v, g_v); SYM(p_r, g_r); SYM(p_r2, g_r2);
    SYM(p_tm, g_tm); SYM(p_cm, g_cm); SYM(p_dp0, g_dp0); SYM(p_dp1, g_dp1);

    __half *A0h,*A0l,*Axkh,*Axkl,*Axvh,*Axvl,*Axrh,*Axrl,*Axk2h,*Axk2l,*Axr2h,*Axr2l;
    __half *Aah,*Aal,*Akkh,*Akkl;
    SYM(A0h,g_A0h); SYM(A0l,g_A0l);
    SYM(Axkh,g_Axkh); SYM(Axkl,g_Axkl); SYM(Axvh,g_Axvh); SYM(Axvl,g_Axvl);
    SYM(Axrh,g_Axrh); SYM(Axrl,g_Axrl); SYM(Axk2h,g_Axk2h); SYM(Axk2l,g_Axk2l);
    SYM(Axr2h,g_Axr2h); SYM(Axr2l,g_Axr2l);
    SYM(Aah,g_Aah); SYM(Aal,g_Aal); SYM(Akkh,g_Akkh); SYM(Akkl,g_Akkl);

    __half *WinTh,*WinTl,*WkTh,*WkTl,*WvTh,*WvTl,*WrTh,*WrTl,*WoTh,*WoTl;
    __half *Wk2Th,*Wk2Tl,*Wv2Th,*Wv2Tl,*Wr2Th,*Wr2Tl,*WdTh,*WdTl,*WoutTh,*WoutTl;
    SYM(WinTh,g_WinTh); SYM(WinTl,g_WinTl);
    SYM(WkTh,g_WkTh); SYM(WkTl,g_WkTl); SYM(WvTh,g_WvTh); SYM(WvTl,g_WvTl);
    SYM(WrTh,g_WrTh); SYM(WrTl,g_WrTl); SYM(WoTh,g_WoTh); SYM(WoTl,g_WoTl);
    SYM(Wk2Th,g_Wk2Th); SYM(Wk2Tl,g_Wk2Tl); SYM(Wv2Th,g_Wv2Th); SYM(Wv2Tl,g_Wv2Tl);
    SYM(Wr2Th,g_Wr2Th); SYM(Wr2Tl,g_Wr2Tl);
    SYM(WdTh,g_WdTh); SYM(WdTl,g_WdTl); SYM(WoutTh,g_WoutTh); SYM(WoutTl,g_WoutTl);

    {
        TSP p{};
        p.w[0] = TSE{Win,    WinTh,  WinTl,  Hh};
        p.w[1] = TSE{Wk,     WkTh,   WkTl,   Hh};
        p.w[2] = TSE{Wv,     WvTh,   WvTl,   Hh};
        p.w[3] = TSE{Wr,     WrTh,   WrTl,   Hh};
        p.w[4] = TSE{Wo,     WoTh,   WoTl,   Hh};
        p.w[5] = TSE{Wk2,    Wk2Th,  Wk2Tl,  Hh};
        p.w[6] = TSE{Wv2,    Wv2Th,  Wv2Tl,  Hh};
        p.w[7] = TSE{Wr2,    Wr2Th,  Wr2Tl,  Hh};
        p.w[8] = TSE{Wdrift, WdTh,   WdTl,   Dd};
        p.w[9] = TSE{Wout,   WoutTh, WoutTl, Dd};
        k_transsplit<<<dim3(64, 64, 10), dim3(32, 8)>>>(p);
    }

    k_init<<<(Bsz * Hh + 255) / 256, 256>>>(enc, sc, lstate, idrift);

    const int NE = Bsz * Hh / 256;
    const dim3 thr(256);
    const dim3 thrM(NT);
    const dim3 gH(Hh / BN, Bsz / BM, 1);    // 32 x 4 = 128 CTAs per z
    const dim3 gD(Dd / BN, Bsz / BM, 1);    // 16 x 4 = 64 CTAs

    auto set_mix = [&](TGP& p, const float* lst){
        p.mixk = mix_k; p.mixv = mix_v; p.mixr = mix_r;
        p.mixk2 = mix_k2; p.mixr2 = mix_r2; p.lst = lst;
    };

    for (int s = 0; s < MAXS; s++) {
        { TGP p{}; p.N = Hh; p.gated = 1; p.bias = b_in; set_mix(p, nullptr);
          p.z[0] = TZ{A0h, A0l, WinTh, WinTl, p_li, nullptr, nullptr, 6, 0, 32, 0};
          k_mma<<<gH, thrM, SMEM_TOT>>>(p); }
        { TGP p{}; p.N = Hh; p.gated = 1;
          p.z[0] = TZ{Axkh,  Axkl,  WkTh,  WkTl,  p_k,  nullptr, nullptr, 0, 0, 32, 0};
          p.z[1] = TZ{Axvh,  Axvl,  WvTh,  WvTl,  p_v,  nullptr, nullptr, 0, 0, 32, 0};
          p.z[2] = TZ{Axrh,  Axrl,  WrTh,  WrTl,  p_r,  nullptr, nullptr, 2, 0, 32, 0};
          p.z[3] = TZ{Axr2h, Axr2l, Wr2Th, Wr2Tl, p_r2, nullptr, nullptr, 2, 0, 32, 0};
          p.z[4] = TZ{Axk2h, Axk2l, Wk2Th, Wk2Tl, nullptr, Akkh, Akkl,    3, 0, 32, 0};
          k_mma<<<dim3(Hh/BN, Bsz/BM, 5), thrM, SMEM_TOT>>>(p); }
        k_cell<<<NE, thr>>>(tfirst, tdec, nullptr, nullptr, 1);
        { TGP p{}; p.N = Hh; p.gated = 1;
          p.z[0] = TZ{Aah,  Aal,  WoTh,  WoTl,  p_tm, nullptr, nullptr, 0, 0, 32, 0};
          p.z[1] = TZ{Akkh, Akkl, Wv2Th, Wv2Tl, p_cm, nullptr, nullptr, 0, 0, 32, 0};
          k_mma<<<dim3(Hh/BN, Bsz/BM, 2), thrM, SMEM_TOT>>>(p); }
        // drift GEMM: A = split(tm + r2*cm) fused in prologue (amode=1), split-K x2
        { TGP p{}; p.N = Dd; p.gated = 1;
          p.z[0] = TZ{nullptr, nullptr, WdTh, WdTl, p_dp0, nullptr, nullptr, 0, 0, 16, 1};
          p.z[1] = TZ{nullptr, nullptr, WdTh, WdTl, p_dp1, nullptr, nullptr, 0, 16, 32, 1};
          k_mma<<<dim3(Dd/BN, Bsz/BM, 2), thrM, SMEM_TOT>>>(p); }
        k_reduce<<<256, 256>>>(sc);
    }

    // ---- commit step (original l_state; never gated) ----
    { TGP p{}; p.N = Hh; p.gated = 0; p.bias = b_in; set_mix(p, lstate);
      p.z[0] = TZ{A0h, A0l, WinTh, WinTl, p_li, nullptr, nullptr, 7, 0, 32, 0};
      k_mma<<<gH, thrM, SMEM_TOT>>>(p); }
    { TGP p{}; p.N = Hh; p.gated = 0;
      p.z[0] = TZ{Axkh,  Axkl,  WkTh,  WkTl,  p_k,  nullptr, nullptr, 0, 0, 32, 0};
      p.z[1] = TZ{Axvh,  Axvl,  WvTh,  WvTl,  p_v,  nullptr, nullptr, 0, 0, 32, 0};
      p.z[2] = TZ{Axrh,  Axrl,  WrTh,  WrTl,  p_r,  nullptr, nullptr, 2, 0, 32, 0};
      p.z[3] = TZ{Axr2h, Axr2l, Wr2Th, Wr2Tl, p_r2, nullptr, nullptr, 2, 0, 32, 0};
      p.z[4] = TZ{Axk2h, Axk2l, Wk2Th, Wk2Tl, nullptr, Akkh, Akkl,    3, 0, 32, 0};
      k_mma<<<dim3(Hh/BN, Bsz/BM, 5), thrM, SMEM_TOT>>>(p); }
    k_cell<<<NE, thr>>>(tfirst, tdec, lstate, out + OFF_NS, 0);
    { TGP p{}; p.N = Hh; p.gated = 0;
      p.z[0] = TZ{Aah,  Aal,  WoTh,  WoTl,  p_tm, nullptr, nullptr, 0, 0, 32, 0};
      p.z[1] = TZ{Akkh, Akkl, Wv2Th, Wv2Tl, p_cm, nullptr, nullptr, 0, 0, 32, 0};
      k_mma<<<dim3(Hh/BN, Bsz/BM, 2), thrM, SMEM_TOT>>>(p); }
    // final_enc GEMM: A fused (amode=1), epi 5
    { TGP p{}; p.N = Dd; p.gated = 0; p.bias = b_out; p.enc = enc;
      p.z[0] = TZ{nullptr, nullptr, WoutTh, WoutTl, out + OFF_ENC, nullptr, nullptr, 5, 0, 32, 1};
      k_mma<<<gD, thrM, SMEM_TOT>>>(p); }
    k_final<<<(Bsz * Dd + 255) / 256, 256>>>(out);
}

// round 14
// speedup vs baseline: 1.1008x; 1.1008x over previous
#include <cuda_runtime.h>
#include <cuda_fp16.h>
#include <math.h>
#include <stdint.h>

#define Bsz 512
#define Dd  1024
#define Hh  2048
#define MAXS 8

#define OFF_ENC    0
#define OFF_NS     (Bsz*Dd)
#define OFF_COMMIT (Bsz*Dd + Bsz*Hh*5)
#define OFF_DRIFT  (OFF_COMMIT + 1)

// ===================== device scratch =====================
__device__ float g_drift[Bsz*Dd];
__device__ float g_dp0[Bsz*Dd];
__device__ float g_dp1[Bsz*Dd];
__device__ float g_li[Bsz*Hh];
__device__ float g_k [Bsz*Hh];
__device__ float g_v [Bsz*Hh];
__device__ float g_r [Bsz*Hh];
__device__ float g_r2[Bsz*Hh];
__device__ float g_tm[Bsz*Hh];
__device__ float g_cm[Bsz*Hh];
__device__ float g_sxx[Bsz*Hh];
__device__ float g_saa[Bsz*Hh];
__device__ float g_sbb[Bsz*Hh];
__device__ float g_spp[Bsz*Hh];
__device__ float g_scc[Bsz*Hh];
__device__ float g_part[256][2];
__device__ float g_csum, g_cnt;
__device__ int   g_done;
__device__ int   g_rcount;

// fp16 split A buffers [512 x 2048]
__device__ __half g_A0h[Bsz*Hh],  g_A0l[Bsz*Hh];
__device__ __half g_Axkh[Bsz*Hh], g_Axkl[Bsz*Hh];
__device__ __half g_Axvh[Bsz*Hh], g_Axvl[Bsz*Hh];
__device__ __half g_Axrh[Bsz*Hh], g_Axrl[Bsz*Hh];
__device__ __half g_Axk2h[Bsz*Hh],g_Axk2l[Bsz*Hh];
__device__ __half g_Axr2h[Bsz*Hh],g_Axr2l[Bsz*Hh];
__device__ __half g_Aah[Bsz*Hh],  g_Aal[Bsz*Hh];
__device__ __half g_Akkh[Bsz*Hh], g_Akkl[Bsz*Hh];
__device__ __half g_Adh[Bsz*Hh],  g_Adl[Bsz*Hh];

// transposed + split weights [N, 2048] fp16
__device__ __half g_WinTh[Hh*2048],  g_WinTl[Hh*2048];
__device__ __half g_WkTh [Hh*Hh],    g_WkTl [Hh*Hh];
__device__ __half g_WvTh [Hh*Hh],    g_WvTl [Hh*Hh];
__device__ __half g_WrTh [Hh*Hh],    g_WrTl [Hh*Hh];
__device__ __half g_WoTh [Hh*Hh],    g_WoTl [Hh*Hh];
__device__ __half g_Wk2Th[Hh*Hh],    g_Wk2Tl[Hh*Hh];
__device__ __half g_Wv2Th[Hh*Hh],    g_Wv2Tl[Hh*Hh];
__device__ __half g_Wr2Th[Hh*Hh],    g_Wr2Tl[Hh*Hh];
__device__ __half g_WdTh [Dd*Hh],    g_WdTl [Dd*Hh];
__device__ __half g_WoutTh[Dd*Hh],   g_WoutTl[Dd*Hh];

__device__ __forceinline__ float clip50(float x){ return fminf(fmaxf(x, -50.f), 50.f); }
__device__ __forceinline__ void split_store(float v, __half* H, __half* L, size_t i){
    __half h = __float2half_rn(v);
    H[i] = h;
    L[i] = __float2half_rn(v - __half2float(h));
}
__device__ __forceinline__ void split2(float v0, float v1, __half* H, __half* L, size_t i){
    __half h0 = __float2half_rn(v0), h1 = __float2half_rn(v1);
    *(__half2*)(H + i) = __halves2half2(h0, h1);
    *(__half2*)(L + i) = __halves2half2(__float2half_rn(v0 - __half2float(h0)),
                                        __float2half_rn(v1 - __half2float(h1)));
}

// ===================== PTX primitives (compute_103-generic) =====================
__device__ __forceinline__ uint32_t smem_u32(const void* p){
    uint32_t a;
    asm("{ .reg .u64 t; cvta.to.shared.u64 t, %1; cvt.u32.u64 %0, t; }" : "=r"(a) : "l"(p));
    return a;
}
__device__ __forceinline__ void cp16(uint32_t s, const void* g){
    asm volatile("cp.async.cg.shared.global [%0], [%1], 16;" :: "r"(s), "l"(g));
}
#define CP_COMMIT() asm volatile("cp.async.commit_group;" ::: "memory")
#define CP_WAIT(n)  asm volatile("cp.async.wait_group %0;" :: "n"(n) : "memory")

__device__ __forceinline__ void ldm4(uint32_t* r, uint32_t a){
    asm volatile("ldmatrix.sync.aligned.m8n8.x4.shared.b16 {%0,%1,%2,%3}, [%4];"
        : "=r"(r[0]), "=r"(r[1]), "=r"(r[2]), "=r"(r[3]) : "r"(a));
}
__device__ __forceinline__ void mma16816(float* d, const uint32_t* a, const uint32_t* b){
    asm volatile("mma.sync.aligned.m16n8k16.row.col.f32.f16.f16.f32 "
        "{%0,%1,%2,%3}, {%4,%5,%6,%7}, {%8,%9}, {%0,%1,%2,%3};"
        : "+f"(d[0]), "+f"(d[1]), "+f"(d[2]), "+f"(d[3])
        : "r"(a[0]), "r"(a[1]), "r"(a[2]), "r"(a[3]), "r"(b[0]), "r"(b[1]));
}

// ===================== weight transpose + split (once per launch) =====================
struct TSE { const float* s; __half *dh, *dl; int nc; };
struct TSP { TSE w[10]; };

__global__ void k_transsplit(TSP p)
{
    TSE e = p.w[blockIdx.z];
    int n0 = blockIdx.y * 32;
    if (n0 >= e.nc) return;
    int k0 = blockIdx.x * 32;
    __shared__ float t[32][33];
    int tx = threadIdx.x, ty = threadIdx.y;
#pragma unroll
    for (int j = 0; j < 4; j++)
        t[ty + j*8][tx] = e.s[(size_t)(k0 + ty + j*8) * e.nc + n0 + tx];
    __syncthreads();
#pragma unroll
    for (int j = 0; j < 4; j++) {
        int n = n0 + ty + j*8, k = k0 + tx;
        float v = t[tx][ty + j*8];
        __half h = __float2half_rn(v);
        e.dh[(size_t)n * 2048 + k] = h;
        e.dl[(size_t)n * 2048 + k] = __float2half_rn(v - __half2float(h));
    }
}

// ===================== HMMA GEMM: 4-plane chunks, 3 fp32 MMA passes, 1 sync/chunk =====================
struct TZ {
    const __half *Ahi, *Alo, *Bhi, *Blo;
    float* C;
    __half *Chi, *Clo;
    int epi; // 0 plain, 1 clip+bias, 2 sigmoid, 3 relu^2->split, 4 tanh,
             // 5 enc+acc+bias, 6 fused li+mix (shadow), 7 fused li+mix (commit lstate)
    int tb, te;  // chunk range (K64 chunks); full = 0..32
};
struct TGP {
    TZ z[5];
    const float* bias;
    const float* enc;
    const float *mixk, *mixv, *mixr, *mixk2, *mixr2, *lst;
    int N, gated;
};

#define BM 128
#define BN 64
#define BKh 64
#define NT 128          /* threads per CTA */
#define STG 2
#define APL_B 16384     /* one A plane per stage */
#define BPL_B 8192      /* one B plane per stage */
#define STG_BYTES (2*APL_B + 2*BPL_B)   /* Ahi, Alo, Bhi, Blo = 48KB */
#define SMEM_TOT (STG*STG_BYTES)        /* 96KB -> 2 CTA/SM */

__global__ __launch_bounds__(NT, 2) void k_mma(TGP p)
{
    if (p.gated && g_done) return;
    extern __shared__ __align__(128) char sm[];
    const uint32_t smb = smem_u32(sm);
    const TZ gz = p.z[blockIdx.z];
    const int tid = threadIdx.x, l = tid & 31, wid = tid >> 5;
    const int m0 = blockIdx.y * BM, n0 = blockIdx.x * BN;
    const int wm = (wid >> 1) * 64, wn = (wid & 1) * 32;  // 2x2 warp grid, 64x32 warp tile

    float acc[4][4][4];
#pragma unroll
    for (int i = 0; i < 4; i++)
#pragma unroll
        for (int j = 0; j < 4; j++)
#pragma unroll
            for (int q = 0; q < 4; q++) acc[i][j][q] = 0.f;

    // cp.async mapping (128 threads): per A plane 1024 vec (8/thread), per B plane 512 vec (4/thread)
    int a_r[8], a_c[8]; uint32_t a_so[8];
#pragma unroll
    for (int i = 0; i < 8; i++) {
        int v = tid + i * NT;
        a_r[i] = v >> 3; a_c[i] = v & 7;
        a_so[i] = (uint32_t)(a_r[i] * 128 + ((a_c[i] ^ (a_r[i] & 7)) << 4));
    }
    int b_r[4], b_c[4]; uint32_t b_so[4];
#pragma unroll
    for (int i = 0; i < 4; i++) {
        int v = tid + i * NT;
        b_r[i] = v >> 3; b_c[i] = v & 7;
        b_so[i] = (uint32_t)(b_r[i] * 128 + ((b_c[i] ^ (b_r[i] & 7)) << 4));
    }

    auto load_stage = [&](int stage, int t){
        int kc = t * BKh;
        uint32_t base = smb + stage * STG_BYTES;
#pragma unroll
        for (int i = 0; i < 8; i++)
            cp16(base + a_so[i], gz.Ahi + (size_t)(m0 + a_r[i]) * 2048 + kc + a_c[i] * 8);
#pragma unroll
        for (int i = 0; i < 8; i++)
            cp16(base + APL_B + a_so[i], gz.Alo + (size_t)(m0 + a_r[i]) * 2048 + kc + a_c[i] * 8);
#pragma unroll
        for (int i = 0; i < 4; i++)
            cp16(base + 2*APL_B + b_so[i], gz.Bhi + (size_t)(n0 + b_r[i]) * 2048 + kc + b_c[i] * 8);
#pragma unroll
        for (int i = 0; i < 4; i++)
            cp16(base + 2*APL_B + BPL_B + b_so[i], gz.Blo + (size_t)(n0 + b_r[i]) * 2048 + kc + b_c[i] * 8);
        CP_COMMIT();
    };

    // ldmatrix lane-constant pieces
    const int ar  = wm + (l & 15);       // + mi*16   (A m16k16 x4)
    const int ahi = (l >> 4) & 1;
    const int bn4 = wn + (l & 7) + ((l >> 4) & 1) * 8;  // B n16k16 x4 (two n8 tiles)
    const int bhi = (l >> 3) & 1;

    load_stage(gz.tb & 1, gz.tb);

    // Single-sync pipeline: wait(chunk t ready) -> sync (all done reading the
    // other stage) -> issue loads for t+1 into that stage -> compute t.
    for (int t = gz.tb; t < gz.te; t++) {
        CP_WAIT(0);
        __syncthreads();
        if (t + 1 < gz.te) load_stage((t + 1) & 1, t + 1);

        uint32_t base = smb + (t & 1) * STG_BYTES;
        uint32_t Ah = base, Al = base + APL_B;
        uint32_t Bh = base + 2*APL_B, Bl = base + 2*APL_B + BPL_B;

#pragma unroll
        for (int kk = 0; kk < 4; kk++) {
            uint32_t ah[4][4], al[4][4], bh[2][4], bl[2][4];
#pragma unroll
            for (int mi = 0; mi < 4; mi++) {
                int r = ar + mi * 16, c = kk * 2 + ahi;
                uint32_t off = (uint32_t)(r * 128 + ((c ^ (r & 7)) << 4));
                ldm4(ah[mi], Ah + off);
                ldm4(al[mi], Al + off);
            }
#pragma unroll
            for (int g = 0; g < 2; g++) {
                int n = bn4 + g * 16, c = kk * 2 + bhi;
                uint32_t off = (uint32_t)(n * 128 + ((c ^ (n & 7)) << 4));
                ldm4(bh[g], Bh + off);
                ldm4(bl[g], Bl + off);
            }
            // pass 1: Ahi * Bhi
#pragma unroll
            for (int mi = 0; mi < 4; mi++)
#pragma unroll
                for (int ni = 0; ni < 4; ni++)
                    mma16816(acc[mi][ni], ah[mi], &bh[ni >> 1][(ni & 1) * 2]);
            // pass 2: Ahi * Blo
#pragma unroll
            for (int mi = 0; mi < 4; mi++)
#pragma unroll
                for (int ni = 0; ni < 4; ni++)
                    mma16816(acc[mi][ni], ah[mi], &bl[ni >> 1][(ni & 1) * 2]);
            // pass 3: Alo * Bhi
#pragma unroll
            for (int mi = 0; mi < 4; mi++)
#pragma unroll
                for (int ni = 0; ni < 4; ni++)
                    mma16816(acc[mi][ni], al[mi], &bh[ni >> 1][(ni & 1) * 2]);
        }
    }

    // ---- epilogue ----
    const int rl = l >> 2, cl = (l & 3) * 2;
    const int N = p.N;
#pragma unroll
    for (int mi = 0; mi < 4; mi++) {
#pragma unroll
        for (int ni = 0; ni < 4; ni++) {
            float* a = acc[mi][ni];
#pragma unroll
            for (int h = 0; h < 2; h++) {
                int r = m0 + wm + mi * 16 + h * 8 + rl;
                int c = n0 + wn + ni * 8 + cl;
                float v0 = a[2*h], v1 = a[2*h + 1];
                size_t i0 = (size_t)r * N + c;

                if (gz.epi >= 6) {
                    float li0 = clip50(v0 + p.bias[c]);
                    float li1 = clip50(v1 + p.bias[c + 1]);
                    *(float2*)(gz.C + i0) = make_float2(li0, li1);
                    float xx0, xx1, cc0, cc1;
                    if (gz.epi == 7) {
                        const float* s = p.lst + i0 * 5;
                        xx0 = s[0]; cc0 = s[4]; xx1 = s[5]; cc1 = s[9];
                    } else {
                        xx0 = g_sxx[i0]; xx1 = g_sxx[i0 + 1];
                        cc0 = g_scc[i0]; cc1 = g_scc[i0 + 1];
                    }
                    float a0, a1;
                    a0 = p.mixk[c];  a1 = p.mixk[c+1];
                    split2(li0*a0 + xx0*(1.f-a0), li1*a1 + xx1*(1.f-a1), g_Axkh,  g_Axkl,  i0);
                    a0 = p.mixv[c];  a1 = p.mixv[c+1];
                    split2(li0*a0 + xx0*(1.f-a0), li1*a1 + xx1*(1.f-a1), g_Axvh,  g_Axvl,  i0);
                    a0 = p.mixr[c];  a1 = p.mixr[c+1];
                    split2(li0*a0 + xx0*(1.f-a0), li1*a1 + xx1*(1.f-a1), g_Axrh,  g_Axrl,  i0);
                    a0 = p.mixk2[c]; a1 = p.mixk2[c+1];
                    split2(li0*a0 + cc0*(1.f-a0), li1*a1 + cc1*(1.f-a1), g_Axk2h, g_Axk2l, i0);
                    a0 = p.mixr2[c]; a1 = p.mixr2[c+1];
                    split2(li0*a0 + cc0*(1.f-a0), li1*a1 + cc1*(1.f-a1), g_Axr2h, g_Axr2l, i0);
                } else if (gz.epi == 3) {
                    float t0 = fmaxf(v0, 0.f); v0 = t0 * t0;
                    float t1 = fmaxf(v1, 0.f); v1 = t1 * t1;
                    split2(v0, v1, gz.Chi, gz.Clo, i0);
                } else {
                    switch (gz.epi) {
                    case 1:
                        v0 = clip50(v0 + p.bias[c]);
                        v1 = clip50(v1 + p.bias[c + 1]);
                        break;
                    case 2:
                        v0 = 1.f / (1.f + expf(-v0));
                        v1 = 1.f / (1.f + expf(-v1));
                        break;
                    case 4:
                        v0 = tanhf(v0); v1 = tanhf(v1);
                        break;
                    case 5:
                        v0 += p.enc[i0]     + p.bias[c];
                        v1 += p.enc[i0 + 1] + p.bias[c + 1];
                        break;
                    default: break;
                    }
                    *(float2*)(gz.C + i0) = make_float2(v0, v1);
                }
            }
        }
    }
}

// ===================== elementwise kernels =====================
__global__ void k_init(const float* enc, const float* sc,
                       const float* lstate, const float* idrift)
{
    int i = blockIdx.x * blockDim.x + threadIdx.x;
    if (i < Bsz * Hh) {
        const float* s = lstate + (size_t)i * 5;
        g_sxx[i] = s[0]; g_saa[i] = s[1]; g_sbb[i] = s[2]; g_spp[i] = s[3]; g_scc[i] = s[4];
    }
    if (i < Bsz * Dd) {
        g_drift[i] = idrift[i];
        int m = i >> 10, col = i & 1023;
        size_t a0 = (size_t)m * 2048 + col;
        split_store(enc[i], g_A0h, g_A0l, a0);
        split_store(sc[i] + idrift[i], g_A0h, g_A0l, a0 + 1024);
    }
    if (i == 0) { g_csum = 0.f; g_cnt = 0.f; g_done = 0; g_rcount = 0; }
}

__global__ void k_cell(const float* tf, const float* td,
                       const float* lstate_in, float* ns_out, int gated)
{
    if (gated && g_done) return;
    int i = blockIdx.x * blockDim.x + threadIdx.x;
    int h = i & (Hh - 1);
    float kx = g_k[i], v = g_v[i], r = g_r[i], li = g_li[i];
    float aa, bb, pp;
    if (lstate_in) {
        const float* s = lstate_in + (size_t)i * 5;
        aa = s[1]; bb = s[2]; pp = s[3];
    } else {
        aa = g_saa[i]; bb = g_sbb[i]; pp = g_spp[i];
    }
    float ww = tf[h] + kx;
    float q  = fmaxf(pp, ww);
    float e1 = expf(pp - q), e2 = expf(ww - q);
    float wkv = (e1 * aa + e2 * v) / (e1 * bb + e2);
    split_store(r * wkv, g_Aah, g_Aal, i);

    float ww2 = pp - expf(td[h]);
    float q2  = fmaxf(ww2, kx);
    float e1b = expf(ww2 - q2), e2b = expf(kx - q2);
    float naa = clip50(e1b * aa + e2b * v);
    float nbb = clip50(e1b * bb + e2b);
    float npp = clip50(q2);
    float nxx = clip50(li);
    if (ns_out) {
        float* o = ns_out + (size_t)i * 5;
        o[0] = nxx; o[1] = naa; o[2] = nbb; o[3] = npp; o[4] = nxx;
    } else {
        g_sxx[i] = nxx; g_saa[i] = naa; g_sbb[i] = nbb; g_spp[i] = npp; g_scc[i] = nxx;
    }
}

__global__ void k_comb(int gated)
{
    if (gated && g_done) return;
    int i = blockIdx.x * blockDim.x + threadIdx.x;
    float v = g_tm[i] + g_r2[i] * g_cm[i];
    split_store(v, g_Adh, g_Adl, i);
}

// drift update (split-K partials + tanh) + A0 refresh + partials + fused final reduce
__global__ void k_reduce(const float* sc)
{
    if (g_done) return;
    __shared__ float sA[256], sB[256];
    __shared__ int isLast;
    int t = threadIdx.x;
    size_t base = (size_t)blockIdx.x * 2048 + t;
    float sa = 0.f, sn = 0.f;
#pragma unroll
    for (int j = 0; j < 8; j++) {
        size_t i = base + (size_t)j * 256;
        float d  = tanhf(g_dp0[i] + g_dp1[i]);
        float nd = fminf(fmaxf(g_drift[i] + d, -5.f), 5.f);
        g_drift[i] = nd;
        int m = (int)(i >> 10), col = (int)(i & 1023);
        split_store(sc[i] + nd, g_A0h, g_A0l, (size_t)m * 2048 + 1024 + col);
        sa += fabsf(d);
        sn += nd * nd;
    }
    sA[t] = sa; sB[t] = sn;
    __syncthreads();
    for (int s = 128; s > 0; s >>= 1) {
        if (t < s) { sA[t] += sA[t + s]; sB[t] += sB[t + s]; }
        __syncthreads();
    }
    if (t == 0) {
        g_part[blockIdx.x][0] = sA[0];
        g_part[blockIdx.x][1] = sB[0];
        __threadfence();
        int c = atomicAdd(&g_rcount, 1);
        isLast = (c == 255);
    }
    __syncthreads();
    if (!isLast) return;

    // last block: final reduce (deterministic — fixed partials, fixed order)
    sA[t] = g_part[t][0]; sB[t] = g_part[t][1];
    __syncthreads();
    for (int s = 128; s > 0; s >>= 1) {
        if (t < s) { sA[t] += sA[t + s]; sB[t] += sB[t + s]; }
        __syncthreads();
    }
    if (t == 0) {
        float hinge = fminf(fmaxf(sB[0] / (float)Bsz - 0.1f, 0.f), 100.f);
        g_csum += hinge;
        g_cnt  += 1.f;
        if (sA[0] * (1.f / (float)(Bsz * Dd)) < 0.01f) g_done = 1;
        g_rcount = 0;
    }
}

__global__ void k_final(float* out)
{
    int i = blockIdx.x * blockDim.x + threadIdx.x;
    if (i < Bsz * Dd) out[OFF_DRIFT + i] = g_drift[i];
    if (i == 0) out[OFF_COMMIT] = g_csum / fmaxf(g_cnt, 1.f);
}

// ===================== host =====================
#define SYM(p, s) cudaGetSymbolAddress((void**)&(p), s)

extern "C" void kernel_launch(void* const* d_in, const int* in_sizes, int n_in,
                              void* d_out, int out_size)
{
    (void)in_sizes; (void)n_in; (void)out_size;
    const float* enc    = (const float*)d_in[0];
    const float* sc     = (const float*)d_in[1];
    const float* lstate = (const float*)d_in[2];
    const float* idrift = (const float*)d_in[3];
    const float* Win    = (const float*)d_in[4];
    const float* b_in   = (const float*)d_in[5];
    const float* Wdrift = (const float*)d_in[6];
    const float* Wout   = (const float*)d_in[7];
    const float* b_out  = (const float*)d_in[8];
    const float* mix_k  = (const float*)d_in[9];
    const float* mix_v  = (const float*)d_in[10];
    const float* mix_r  = (const float*)d_in[11];
    const float* mix_k2 = (const float*)d_in[12];
    const float* mix_r2 = (const float*)d_in[13];
    const float* tdec   = (const float*)d_in[14];
    const float* tfirst = (const float*)d_in[15];
    const float* Wk  = (const float*)d_in[16];
    const float* Wv  = (const float*)d_in[17];
    const float* Wr  = (const float*)d_in[18];
    const float* Wo  = (const float*)d_in[19];
    const float* Wk2 = (const float*)d_in[20];
    const float* Wv2 = (const float*)d_in[21];
    const float* Wr2 = (const float*)d_in[22];
    float* out = (float*)d_out;

    cudaFuncSetAttribute(k_mma, cudaFuncAttributeMaxDynamicSharedMemorySize, SMEM_TOT);

    float *p_li, *p_k, *p_v, *p_r, *p_r2, *p_tm, *p_cm, *p_dp0, *p_dp1;
    SYM(p_li, g_li); SYM(p_k, g_k); SYM(p_v, g_v); SYM(p_r, g_r); SYM(p_r2, g_r2);
    SYM(p_tm, g_tm); SYM(p_cm, g_cm); SYM(p_dp0, g_dp0); SYM(p_dp1, g_dp1);

    __half *A0h,*A0l,*Axkh,*Axkl,*Axvh,*Axvl,*Axrh,*Axrl,*Axk2h,*Axk2l,*Axr2h,*Axr2l;
    __half *Aah,*Aal,*Akkh,*Akkl,*Adh,*Adl;
    SYM(A0h,g_A0h); SYM(A0l,g_A0l);
    SYM(Axkh,g_Axkh); SYM(Axkl,g_Axkl); SYM(Axvh,g_Axvh); SYM(Axvl,g_Axvl);
    SYM(Axrh,g_Axrh); SYM(Axrl,g_Axrl); SYM(Axk2h,g_Axk2h); SYM(Axk2l,g_Axk2l);
    SYM(Axr2h,g_Axr2h); SYM(Axr2l,g_Axr2l);
    SYM(Aah,g_Aah); SYM(Aal,g_Aal); SYM(Akkh,g_Akkh); SYM(Akkl,g_Akkl);
    SYM(Adh,g_Adh); SYM(Adl,g_Adl);

    __half *WinTh,*WinTl,*WkTh,*WkTl,*WvTh,*WvTl,*WrTh,*WrTl,*WoTh,*WoTl;
    __half *Wk2Th,*Wk2Tl,*Wv2Th,*Wv2Tl,*Wr2Th,*Wr2Tl,*WdTh,*WdTl,*WoutTh,*WoutTl;
    SYM(WinTh,g_WinTh); SYM(WinTl,g_WinTl);
    SYM(WkTh,g_WkTh); SYM(WkTl,g_WkTl); SYM(WvTh,g_WvTh); SYM(WvTl,g_WvTl);
    SYM(WrTh,g_WrTh); SYM(WrTl,g_WrTl); SYM(WoTh,g_WoTh); SYM(WoTl,g_WoTl);
    SYM(Wk2Th,g_Wk2Th); SYM(Wk2Tl,g_Wk2Tl); SYM(Wv2Th,g_Wv2Th); SYM(Wv2Tl,g_Wv2Tl);
    SYM(Wr2Th,g_Wr2Th); SYM(Wr2Tl,g_Wr2Tl);
    SYM(WdTh,g_WdTh); SYM(WdTl,g_WdTl); SYM(WoutTh,g_WoutTh); SYM(WoutTl,g_WoutTl);

    {
        TSP p{};
        p.w[0] = TSE{Win,    WinTh,  WinTl,  Hh};
        p.w[1] = TSE{Wk,     WkTh,   WkTl,   Hh};
        p.w[2] = TSE{Wv,     WvTh,   WvTl,   Hh};
        p.w[3] = TSE{Wr,     WrTh,   WrTl,   Hh};
        p.w[4] = TSE{Wo,     WoTh,   WoTl,   Hh};
        p.w[5] = TSE{Wk2,    Wk2Th,  Wk2Tl,  Hh};
        p.w[6] = TSE{Wv2,    Wv2Th,  Wv2Tl,  Hh};
        p.w[7] = TSE{Wr2,    Wr2Th,  Wr2Tl,  Hh};
        p.w[8] = TSE{Wdrift, WdTh,   WdTl,   Dd};
        p.w[9] = TSE{Wout,   WoutTh, WoutTl, Dd};
        k_transsplit<<<dim3(64, 64, 10), dim3(32, 8)>>>(p);
    }

    k_init<<<(Bsz * Hh + 255) / 256, 256>>>(enc, sc, lstate, idrift);

    const int NE = Bsz * Hh / 256;
    const dim3 thr(256);
    const dim3 thrM(NT);
    const dim3 gH(Hh / BN, Bsz / BM, 1);    // 32 x 4 = 128 CTAs per z
    const dim3 gD(Dd / BN, Bsz / BM, 1);    // 16 x 4 = 64 CTAs

    auto set_mix = [&](TGP& p, const float* lst){
        p.mixk = mix_k; p.mixv = mix_v; p.mixr = mix_r;
        p.mixk2 = mix_k2; p.mixr2 = mix_r2; p.lst = lst;
    };

    for (int s = 0; s < MAXS; s++) {
        { TGP p{}; p.N = Hh; p.gated = 1; p.bias = b_in; set_mix(p, nullptr);
          p.z[0] = TZ{A0h, A0l, WinTh, WinTl, p_li, nullptr, nullptr, 6, 0, 32};
          k_mma<<<gH, thrM, SMEM_TOT>>>(p); }
        { TGP p{}; p.N = Hh; p.gated = 1;
          p.z[0] = TZ{Axkh,  Axkl,  WkTh,  WkTl,  p_k,  nullptr, nullptr, 0, 0, 32};
          p.z[1] = TZ{Axvh,  Axvl,  WvTh,  WvTl,  p_v,  nullptr, nullptr, 0, 0, 32};
          p.z[2] = TZ{Axrh,  Axrl,  WrTh,  WrTl,  p_r,  nullptr, nullptr, 2, 0, 32};
          p.z[3] = TZ{Axr2h, Axr2l, Wr2Th, Wr2Tl, p_r2, nullptr, nullptr, 2, 0, 32};
          p.z[4] = TZ{Axk2h, Axk2l, Wk2Th, Wk2Tl, nullptr, Akkh, Akkl,    3, 0, 32};
          k_mma<<<dim3(Hh/BN, Bsz/BM, 5), thrM, SMEM_TOT>>>(p); }
        k_cell<<<NE, thr>>>(tfirst, tdec, nullptr, nullptr, 1);
        { TGP p{}; p.N = Hh; p.gated = 1;
          p.z[0] = TZ{Aah,  Aal,  WoTh,  WoTl,  p_tm, nullptr, nullptr, 0, 0, 32};
          p.z[1] = TZ{Akkh, Akkl, Wv2Th, Wv2Tl, p_cm, nullptr, nullptr, 0, 0, 32};
          k_mma<<<dim3(Hh/BN, Bsz/BM, 2), thrM, SMEM_TOT>>>(p); }
        k_comb<<<NE, thr>>>(1);
        // split-K x2 Wdrift GEMM: 128 CTAs instead of 64
        { TGP p{}; p.N = Dd; p.gated = 1;
          p.z[0] = TZ{Adh, Adl, WdTh, WdTl, p_dp0, nullptr, nullptr, 0, 0, 16};
          p.z[1] = TZ{Adh, Adl, WdTh, WdTl, p_dp1, nullptr, nullptr, 0, 16, 32};
          k_mma<<<dim3(Dd/BN, Bsz/BM, 2), thrM, SMEM_TOT>>>(p); }
        k_reduce<<<256, 256>>>(sc);
    }

    // ---- commit step (original l_state; never gated) ----
    { TGP p{}; p.N = Hh; p.gated = 0; p.bias = b_in; set_mix(p, lstate);
      p.z[0] = TZ{A0h, A0l, WinTh, WinTl, p_li, nullptr, nullptr, 7, 0, 32};
      k_mma<<<gH, thrM, SMEM_TOT>>>(p); }
    { TGP p{}; p.N = Hh; p.gated = 0;
      p.z[0] = TZ{Axkh,  Axkl,  WkTh,  WkTl,  p_k,  nullptr, nullptr, 0, 0, 32};
      p.z[1] = TZ{Axvh,  Axvl,  WvTh,  WvTl,  p_v,  nullptr, nullptr, 0, 0, 32};
      p.z[2] = TZ{Axrh,  Axrl,  WrTh,  WrTl,  p_r,  nullptr, nullptr, 2, 0, 32};
      p.z[3] = TZ{Axr2h, Axr2l, Wr2Th, Wr2Tl, p_r2, nullptr, nullptr, 2, 0, 32};
      p.z[4] = TZ{Axk2h, Axk2l, Wk2Th, Wk2Tl, nullptr, Akkh, Akkl,    3, 0, 32};
      k_mma<<<dim3(Hh/BN, Bsz/BM, 5), thrM, SMEM_TOT>>>(p); }
    k_cell<<<NE, thr>>>(tfirst, tdec, lstate, out + OFF_NS, 0);
    { TGP p{}; p.N = Hh; p.gated = 0;
      p.z[0] = TZ{Aah,  Aal,  WoTh,  WoTl,  p_tm, nullptr, nullptr, 0, 0, 32};
      p.z[1] = TZ{Akkh, Akkl, Wv2Th, Wv2Tl, p_cm, nullptr, nullptr, 0, 0, 32};
      k_mma<<<dim3(Hh/BN, Bsz/BM, 2), thrM, SMEM_TOT>>>(p); }
    k_comb<<<NE, thr>>>(0);
    { TGP p{}; p.N = Dd; p.gated = 0; p.bias = b_out; p.enc = enc;
      p.z[0] = TZ{Adh, Adl, WoutTh, WoutTl, out + OFF_ENC, nullptr, nullptr, 5, 0, 32};
      k_mma<<<gD, thrM, SMEM_TOT>>>(p); }
    k_final<<<(Bsz * Dd + 255) / 256, 256>>>(out);
}

// round 15
// speedup vs baseline: 1.2185x; 1.1069x over previous
#include <cuda_runtime.h>
#include <cuda_fp16.h>
#include <math.h>
#include <stdint.h>

#define Bsz 512
#define Dd  1024
#define Hh  2048
#define MAXS 8

#define OFF_ENC    0
#define OFF_NS     (Bsz*Dd)
#define OFF_COMMIT (Bsz*Dd + Bsz*Hh*5)
#define OFF_DRIFT  (OFF_COMMIT + 1)

// ===================== device scratch =====================
__device__ float g_drift[Bsz*Dd];
__device__ float g_dp0[Bsz*Dd];
__device__ float g_dp1[Bsz*Dd];
__device__ float g_lp0[Bsz*Hh];
__device__ float g_lp1[Bsz*Hh];
__device__ float g_li[Bsz*Hh];
__device__ float g_k [Bsz*Hh];
__device__ float g_v [Bsz*Hh];
__device__ float g_r [Bsz*Hh];
__device__ float g_r2[Bsz*Hh];
__device__ float g_tm[Bsz*Hh];
__device__ float g_cm[Bsz*Hh];
__device__ float g_sxx[Bsz*Hh];
__device__ float g_saa[Bsz*Hh];
__device__ float g_sbb[Bsz*Hh];
__device__ float g_spp[Bsz*Hh];
__device__ float g_scc[Bsz*Hh];
__device__ float g_part[256][2];
__device__ float g_csum, g_cnt;
__device__ int   g_done;
__device__ int   g_rcount;

// fp16 split A buffers [512 x 2048]
__device__ __half g_A0h[Bsz*Hh],  g_A0l[Bsz*Hh];
__device__ __half g_Axkh[Bsz*Hh], g_Axkl[Bsz*Hh];
__device__ __half g_Axvh[Bsz*Hh], g_Axvl[Bsz*Hh];
__device__ __half g_Axrh[Bsz*Hh], g_Axrl[Bsz*Hh];
__device__ __half g_Axk2h[Bsz*Hh],g_Axk2l[Bsz*Hh];
__device__ __half g_Axr2h[Bsz*Hh],g_Axr2l[Bsz*Hh];
__device__ __half g_Aah[Bsz*Hh],  g_Aal[Bsz*Hh];
__device__ __half g_Akkh[Bsz*Hh], g_Akkl[Bsz*Hh];
__device__ __half g_Adh[Bsz*Hh],  g_Adl[Bsz*Hh];

// transposed + split weights [N, 2048] fp16
__device__ __half g_WinTh[Hh*2048],  g_WinTl[Hh*2048];
__device__ __half g_WkTh [Hh*Hh],    g_WkTl [Hh*Hh];
__device__ __half g_WvTh [Hh*Hh],    g_WvTl [Hh*Hh];
__device__ __half g_WrTh [Hh*Hh],    g_WrTl [Hh*Hh];
__device__ __half g_WoTh [Hh*Hh],    g_WoTl [Hh*Hh];
__device__ __half g_Wk2Th[Hh*Hh],    g_Wk2Tl[Hh*Hh];
__device__ __half g_Wv2Th[Hh*Hh],    g_Wv2Tl[Hh*Hh];
__device__ __half g_Wr2Th[Hh*Hh],    g_Wr2Tl[Hh*Hh];
__device__ __half g_WdTh [Dd*Hh],    g_WdTl [Dd*Hh];
__device__ __half g_WoutTh[Dd*Hh],   g_WoutTl[Dd*Hh];

__device__ __forceinline__ float clip50(float x){ return fminf(fmaxf(x, -50.f), 50.f); }
__device__ __forceinline__ void split_store(float v, __half* H, __half* L, size_t i){
    __half h = __float2half_rn(v);
    H[i] = h;
    L[i] = __float2half_rn(v - __half2float(h));
}
__device__ __forceinline__ void split2(float v0, float v1, __half* H, __half* L, size_t i){
    __half h0 = __float2half_rn(v0), h1 = __float2half_rn(v1);
    *(__half2*)(H + i) = __halves2half2(h0, h1);
    *(__half2*)(L + i) = __halves2half2(__float2half_rn(v0 - __half2float(h0)),
                                        __float2half_rn(v1 - __half2float(h1)));
}

// ===================== PTX primitives (compute_103-generic) =====================
__device__ __forceinline__ uint32_t smem_u32(const void* p){
    uint32_t a;
    asm("{ .reg .u64 t; cvta.to.shared.u64 t, %1; cvt.u32.u64 %0, t; }" : "=r"(a) : "l"(p));
    return a;
}
__device__ __forceinline__ void cp16(uint32_t s, const void* g){
    asm volatile("cp.async.cg.shared.global [%0], [%1], 16;" :: "r"(s), "l"(g));
}
#define CP_COMMIT() asm volatile("cp.async.commit_group;" ::: "memory")
#define CP_WAIT(n)  asm volatile("cp.async.wait_group %0;" :: "n"(n) : "memory")

__device__ __forceinline__ void ldm4(uint32_t* r, uint32_t a){
    asm volatile("ldmatrix.sync.aligned.m8n8.x4.shared.b16 {%0,%1,%2,%3}, [%4];"
        : "=r"(r[0]), "=r"(r[1]), "=r"(r[2]), "=r"(r[3]) : "r"(a));
}
__device__ __forceinline__ void mma16816(float* d, const uint32_t* a, const uint32_t* b){
    asm volatile("mma.sync.aligned.m16n8k16.row.col.f32.f16.f16.f32 "
        "{%0,%1,%2,%3}, {%4,%5,%6,%7}, {%8,%9}, {%0,%1,%2,%3};"
        : "+f"(d[0]), "+f"(d[1]), "+f"(d[2]), "+f"(d[3])
        : "r"(a[0]), "r"(a[1]), "r"(a[2]), "r"(a[3]), "r"(b[0]), "r"(b[1]));
}

// ===================== weight transpose + split (once per launch) =====================
struct TSE { const float* s; __half *dh, *dl; int nc; };
struct TSP { TSE w[10]; };

__global__ void k_transsplit(TSP p)
{
    TSE e = p.w[blockIdx.z];
    int n0 = blockIdx.y * 32;
    if (n0 >= e.nc) return;
    int k0 = blockIdx.x * 32;
    __shared__ float t[32][33];
    int tx = threadIdx.x, ty = threadIdx.y;
#pragma unroll
    for (int j = 0; j < 4; j++)
        t[ty + j*8][tx] = e.s[(size_t)(k0 + ty + j*8) * e.nc + n0 + tx];
    __syncthreads();
#pragma unroll
    for (int j = 0; j < 4; j++) {
        int n = n0 + ty + j*8, k = k0 + tx;
        float v = t[tx][ty + j*8];
        __half h = __float2half_rn(v);
        e.dh[(size_t)n * 2048 + k] = h;
        e.dl[(size_t)n * 2048 + k] = __float2half_rn(v - __half2float(h));
    }
}

// ===================== HMMA GEMM: 4-plane chunks, 3 fp32 MMA passes, 1 sync/chunk =====================
struct TZ {
    const __half *Ahi, *Alo, *Bhi, *Blo;
    float* C;
    __half *Chi, *Clo;
    int epi; // 0 plain, 1 clip+bias, 2 sigmoid, 3 relu^2->split, 4 tanh, 5 enc+acc+bias
    int tb, te;  // chunk range (K64 chunks); full = 0..32
};
struct TGP {
    TZ z[5];
    const float* bias;
    const float* enc;
    int N, gated;
};

#define BM 128
#define BN 64
#define BKh 64
#define NT 128          /* threads per CTA */
#define STG 2
#define APL_B 16384     /* one A plane per stage */
#define BPL_B 8192      /* one B plane per stage */
#define STG_BYTES (2*APL_B + 2*BPL_B)   /* Ahi, Alo, Bhi, Blo = 48KB */
#define SMEM_TOT (STG*STG_BYTES)        /* 96KB -> 2 CTA/SM */

__global__ __launch_bounds__(NT, 2) void k_mma(TGP p)
{
    if (p.gated && g_done) return;
    extern __shared__ __align__(128) char sm[];
    const uint32_t smb = smem_u32(sm);
    const TZ gz = p.z[blockIdx.z];
    const int tid = threadIdx.x, l = tid & 31, wid = tid >> 5;
    const int m0 = blockIdx.y * BM, n0 = blockIdx.x * BN;
    const int wm = (wid >> 1) * 64, wn = (wid & 1) * 32;  // 2x2 warp grid, 64x32 warp tile

    float acc[4][4][4];
#pragma unroll
    for (int i = 0; i < 4; i++)
#pragma unroll
        for (int j = 0; j < 4; j++)
#pragma unroll
            for (int q = 0; q < 4; q++) acc[i][j][q] = 0.f;

    int a_r[8], a_c[8]; uint32_t a_so[8];
#pragma unroll
    for (int i = 0; i < 8; i++) {
        int v = tid + i * NT;
        a_r[i] = v >> 3; a_c[i] = v & 7;
        a_so[i] = (uint32_t)(a_r[i] * 128 + ((a_c[i] ^ (a_r[i] & 7)) << 4));
    }
    int b_r[4], b_c[4]; uint32_t b_so[4];
#pragma unroll
    for (int i = 0; i < 4; i++) {
        int v = tid + i * NT;
        b_r[i] = v >> 3; b_c[i] = v & 7;
        b_so[i] = (uint32_t)(b_r[i] * 128 + ((b_c[i] ^ (b_r[i] & 7)) << 4));
    }

    auto load_stage = [&](int stage, int t){
        int kc = t * BKh;
        uint32_t base = smb + stage * STG_BYTES;
#pragma unroll
        for (int i = 0; i < 8; i++)
            cp16(base + a_so[i], gz.Ahi + (size_t)(m0 + a_r[i]) * 2048 + kc + a_c[i] * 8);
#pragma unroll
        for (int i = 0; i < 8; i++)
            cp16(base + APL_B + a_so[i], gz.Alo + (size_t)(m0 + a_r[i]) * 2048 + kc + a_c[i] * 8);
#pragma unroll
        for (int i = 0; i < 4; i++)
            cp16(base + 2*APL_B + b_so[i], gz.Bhi + (size_t)(n0 + b_r[i]) * 2048 + kc + b_c[i] * 8);
#pragma unroll
        for (int i = 0; i < 4; i++)
            cp16(base + 2*APL_B + BPL_B + b_so[i], gz.Blo + (size_t)(n0 + b_r[i]) * 2048 + kc + b_c[i] * 8);
        CP_COMMIT();
    };

    const int ar  = wm + (l & 15);
    const int ahi = (l >> 4) & 1;
    const int bn4 = wn + (l & 7) + ((l >> 4) & 1) * 8;
    const int bhi = (l >> 3) & 1;

    load_stage(gz.tb & 1, gz.tb);

    for (int t = gz.tb; t < gz.te; t++) {
        CP_WAIT(0);
        __syncthreads();
        if (t + 1 < gz.te) load_stage((t + 1) & 1, t + 1);

        uint32_t base = smb + (t & 1) * STG_BYTES;
        uint32_t Ah = base, Al = base + APL_B;
        uint32_t Bh = base + 2*APL_B, Bl = base + 2*APL_B + BPL_B;

#pragma unroll
        for (int kk = 0; kk < 4; kk++) {
            uint32_t ah[4][4], al[4][4], bh[2][4], bl[2][4];
#pragma unroll
            for (int mi = 0; mi < 4; mi++) {
                int r = ar + mi * 16, c = kk * 2 + ahi;
                uint32_t off = (uint32_t)(r * 128 + ((c ^ (r & 7)) << 4));
                ldm4(ah[mi], Ah + off);
                ldm4(al[mi], Al + off);
            }
#pragma unroll
            for (int g = 0; g < 2; g++) {
                int n = bn4 + g * 16, c = kk * 2 + bhi;
                uint32_t off = (uint32_t)(n * 128 + ((c ^ (n & 7)) << 4));
                ldm4(bh[g], Bh + off);
                ldm4(bl[g], Bl + off);
            }
#pragma unroll
            for (int mi = 0; mi < 4; mi++)
#pragma unroll
                for (int ni = 0; ni < 4; ni++)
                    mma16816(acc[mi][ni], ah[mi], &bh[ni >> 1][(ni & 1) * 2]);
#pragma unroll
            for (int mi = 0; mi < 4; mi++)
#pragma unroll
                for (int ni = 0; ni < 4; ni++)
                    mma16816(acc[mi][ni], ah[mi], &bl[ni >> 1][(ni & 1) * 2]);
#pragma unroll
            for (int mi = 0; mi < 4; mi++)
#pragma unroll
                for (int ni = 0; ni < 4; ni++)
                    mma16816(acc[mi][ni], al[mi], &bh[ni >> 1][(ni & 1) * 2]);
        }
    }

    // ---- epilogue ----
    const int rl = l >> 2, cl = (l & 3) * 2;
    const int N = p.N;
#pragma unroll
    for (int mi = 0; mi < 4; mi++) {
#pragma unroll
        for (int ni = 0; ni < 4; ni++) {
            float* a = acc[mi][ni];
#pragma unroll
            for (int h = 0; h < 2; h++) {
                int r = m0 + wm + mi * 16 + h * 8 + rl;
                int c = n0 + wn + ni * 8 + cl;
                float v0 = a[2*h], v1 = a[2*h + 1];
                size_t i0 = (size_t)r * N + c;

                if (gz.epi == 3) {
                    float t0 = fmaxf(v0, 0.f); v0 = t0 * t0;
                    float t1 = fmaxf(v1, 0.f); v1 = t1 * t1;
                    split2(v0, v1, gz.Chi, gz.Clo, i0);
                } else {
                    switch (gz.epi) {
                    case 1:
                        v0 = clip50(v0 + p.bias[c]);
                        v1 = clip50(v1 + p.bias[c + 1]);
                        break;
                    case 2:
                        v0 = 1.f / (1.f + expf(-v0));
                        v1 = 1.f / (1.f + expf(-v1));
                        break;
                    case 4:
                        v0 = tanhf(v0); v1 = tanhf(v1);
                        break;
                    case 5:
                        v0 += p.enc[i0]     + p.bias[c];
                        v1 += p.enc[i0 + 1] + p.bias[c + 1];
                        break;
                    default: break;
                    }
                    *(float2*)(gz.C + i0) = make_float2(v0, v1);
                }
            }
        }
    }
}

// ===================== elementwise kernels =====================
__global__ void k_init(const float* enc, const float* sc,
                       const float* lstate, const float* idrift)
{
    int i = blockIdx.x * blockDim.x + threadIdx.x;
    if (i < Bsz * Hh) {
        const float* s = lstate + (size_t)i * 5;
        g_sxx[i] = s[0]; g_saa[i] = s[1]; g_sbb[i] = s[2]; g_spp[i] = s[3]; g_scc[i] = s[4];
    }
    if (i < Bsz * Dd) {
        g_drift[i] = idrift[i];
        int m = i >> 10, col = i & 1023;
        size_t a0 = (size_t)m * 2048 + col;
        split_store(enc[i], g_A0h, g_A0l, a0);
        split_store(sc[i] + idrift[i], g_A0h, g_A0l, a0 + 1024);
    }
    if (i == 0) { g_csum = 0.f; g_cnt = 0.f; g_done = 0; g_rcount = 0; }
}

// combine split-K li partials + bias + clip, then compute 5 mixed split operands
__global__ void k_mix(const float* bias,
                      const float* mk, const float* mv, const float* mr,
                      const float* mk2, const float* mr2,
                      const float* lstate, int gated)
{
    if (gated && g_done) return;
    int i = blockIdx.x * blockDim.x + threadIdx.x;
    int h = i & (Hh - 1);
    float li = clip50(g_lp0[i] + g_lp1[i] + bias[h]);
    g_li[i] = li;
    float xx, cc;
    if (lstate) { xx = lstate[(size_t)i*5 + 0]; cc = lstate[(size_t)i*5 + 4]; }
    else        { xx = g_sxx[i];                cc = g_scc[i]; }
    float a;
    a = mk[h];  split_store(li*a + xx*(1.f-a), g_Axkh,  g_Axkl,  i);
    a = mv[h];  split_store(li*a + xx*(1.f-a), g_Axvh,  g_Axvl,  i);
    a = mr[h];  split_store(li*a + xx*(1.f-a), g_Axrh,  g_Axrl,  i);
    a = mk2[h]; split_store(li*a + cc*(1.f-a), g_Axk2h, g_Axk2l, i);
    a = mr2[h]; split_store(li*a + cc*(1.f-a), g_Axr2h, g_Axr2l, i);
}

__global__ void k_cell(const float* tf, const float* td,
                       const float* lstate_in, float* ns_out, int gated)
{
    if (gated && g_done) return;
    int i = blockIdx.x * blockDim.x + threadIdx.x;
    int h = i & (Hh - 1);
    float kx = g_k[i], v = g_v[i], r = g_r[i], li = g_li[i];
    float aa, bb, pp;
    if (lstate_in) {
        const float* s = lstate_in + (size_t)i * 5;
        aa = s[1]; bb = s[2]; pp = s[3];
    } else {
        aa = g_saa[i]; bb = g_sbb[i]; pp = g_spp[i];
    }
    float ww = tf[h] + kx;
    float q  = fmaxf(pp, ww);
    float e1 = expf(pp - q), e2 = expf(ww - q);
    float wkv = (e1 * aa + e2 * v) / (e1 * bb + e2);
    split_store(r * wkv, g_Aah, g_Aal, i);

    float ww2 = pp - expf(td[h]);
    float q2  = fmaxf(ww2, kx);
    float e1b = expf(ww2 - q2), e2b = expf(kx - q2);
    float naa = clip50(e1b * aa + e2b * v);
    float nbb = clip50(e1b * bb + e2b);
    float npp = clip50(q2);
    float nxx = clip50(li);
    if (ns_out) {
        float* o = ns_out + (size_t)i * 5;
        o[0] = nxx; o[1] = naa; o[2] = nbb; o[3] = npp; o[4] = nxx;
    } else {
        g_sxx[i] = nxx; g_saa[i] = naa; g_sbb[i] = nbb; g_spp[i] = npp; g_scc[i] = nxx;
    }
}

__global__ void k_comb(int gated)
{
    if (gated && g_done) return;
    int i = blockIdx.x * blockDim.x + threadIdx.x;
    float v = g_tm[i] + g_r2[i] * g_cm[i];
    split_store(v, g_Adh, g_Adl, i);
}

// drift update (split-K partials + tanh) + A0 refresh + partials + fused final reduce
__global__ void k_reduce(const float* sc)
{
    if (g_done) return;
    __shared__ float sA[256], sB[256];
    __shared__ int isLast;
    int t = threadIdx.x;
    size_t base = (size_t)blockIdx.x * 2048 + t;
    float sa = 0.f, sn = 0.f;
#pragma unroll
    for (int j = 0; j < 8; j++) {
        size_t i = base + (size_t)j * 256;
        float d  = tanhf(g_dp0[i] + g_dp1[i]);
        float nd = fminf(fmaxf(g_drift[i] + d, -5.f), 5.f);
        g_drift[i] = nd;
        int m = (int)(i >> 10), col = (int)(i & 1023);
        split_store(sc[i] + nd, g_A0h, g_A0l, (size_t)m * 2048 + 1024 + col);
        sa += fabsf(d);
        sn += nd * nd;
    }
    sA[t] = sa; sB[t] = sn;
    __syncthreads();
    for (int s = 128; s > 0; s >>= 1) {
        if (t < s) { sA[t] += sA[t + s]; sB[t] += sB[t + s]; }
        __syncthreads();
    }
    if (t == 0) {
        g_part[blockIdx.x][0] = sA[0];
        g_part[blockIdx.x][1] = sB[0];
        __threadfence();
        int c = atomicAdd(&g_rcount, 1);
        isLast = (c == 255);
    }
    __syncthreads();
    if (!isLast) return;

    sA[t] = g_part[t][0]; sB[t] = g_part[t][1];
    __syncthreads();
    for (int s = 128; s > 0; s >>= 1) {
        if (t < s) { sA[t] += sA[t + s]; sB[t] += sB[t + s]; }
        __syncthreads();
    }
    if (t == 0) {
        float hinge = fminf(fmaxf(sB[0] / (float)Bsz - 0.1f, 0.f), 100.f);
        g_csum += hinge;
        g_cnt  += 1.f;
        if (sA[0] * (1.f / (float)(Bsz * Dd)) < 0.01f) g_done = 1;
        g_rcount = 0;
    }
}

__global__ void k_final(float* out)
{
    int i = blockIdx.x * blockDim.x + threadIdx.x;
    if (i < Bsz * Dd) out[OFF_DRIFT + i] = g_drift[i];
    if (i == 0) out[OFF_COMMIT] = g_csum / fmaxf(g_cnt, 1.f);
}

// ===================== host =====================
#define SYM(p, s) cudaGetSymbolAddress((void**)&(p), s)

extern "C" void kernel_launch(void* const* d_in, const int* in_sizes, int n_in,
                              void* d_out, int out_size)
{
    (void)in_sizes; (void)n_in; (void)out_size;
    const float* enc    = (const float*)d_in[0];
    const float* sc     = (const float*)d_in[1];
    const float* lstate = (const float*)d_in[2];
    const float* idrift = (const float*)d_in[3];
    const float* Win    = (const float*)d_in[4];
    const float* b_in   = (const float*)d_in[5];
    const float* Wdrift = (const float*)d_in[6];
    const float* Wout   = (const float*)d_in[7];
    const float* b_out  = (const float*)d_in[8];
    const float* mix_k  = (const float*)d_in[9];
    const float* mix_v  = (const float*)d_in[10];
    const float* mix_r  = (const float*)d_in[11];
    const float* mix_k2 = (const float*)d_in[12];
    const float* mix_r2 = (const float*)d_in[13];
    const float* tdec   = (const float*)d_in[14];
    const float* tfirst = (const float*)d_in[15];
    const float* Wk  = (const float*)d_in[16];
    const float* Wv  = (const float*)d_in[17];
    const float* Wr  = (const float*)d_in[18];
    const float* Wo  = (const float*)d_in[19];
    const float* Wk2 = (const float*)d_in[20];
    const float* Wv2 = (const float*)d_in[21];
    const float* Wr2 = (const float*)d_in[22];
    float* out = (float*)d_out;

    cudaFuncSetAttribute(k_mma, cudaFuncAttributeMaxDynamicSharedMemorySize, SMEM_TOT);

    float *p_li, *p_k, *p_v, *p_r, *p_r2, *p_tm, *p_cm, *p_dp0, *p_dp1, *p_lp0, *p_lp1;
    SYM(p_li, g_li); SYM(p_k, g_k); SYM(p_v, g_v); SYM(p_r, g_r); SYM(p_r2, g_r2);
    SYM(p_tm, g_tm); SYM(p_cm, g_cm); SYM(p_dp0, g_dp0); SYM(p_dp1, g_dp1);
    SYM(p_lp0, g_lp0); SYM(p_lp1, g_lp1);

    __half *A0h,*A0l,*Axkh,*Axkl,*Axvh,*Axvl,*Axrh,*Axrl,*Axk2h,*Axk2l,*Axr2h,*Axr2l;
    __half *Aah,*Aal,*Akkh,*Akkl,*Adh,*Adl;
    SYM(A0h,g_A0h); SYM(A0l,g_A0l);
    SYM(Axkh,g_Axkh); SYM(Axkl,g_Axkl); SYM(Axvh,g_Axvh); SYM(Axvl,g_Axvl);
    SYM(Axrh,g_Axrh); SYM(Axrl,g_Axrl); SYM(Axk2h,g_Axk2h); SYM(Axk2l,g_Axk2l);
    SYM(Axr2h,g_Axr2h); SYM(Axr2l,g_Axr2l);
    SYM(Aah,g_Aah); SYM(Aal,g_Aal); SYM(Akkh,g_Akkh); SYM(Akkl,g_Akkl);
    SYM(Adh,g_Adh); SYM(Adl,g_Adl);

    __half *WinTh,*WinTl,*WkTh,*WkTl,*WvTh,*WvTl,*WrTh,*WrTl,*WoTh,*WoTl;
    __half *Wk2Th,*Wk2Tl,*Wv2Th,*Wv2Tl,*Wr2Th,*Wr2Tl,*WdTh,*WdTl,*WoutTh,*WoutTl;
    SYM(WinTh,g_WinTh); SYM(WinTl,g_WinTl);
    SYM(WkTh,g_WkTh); SYM(WkTl,g_WkTl); SYM(WvTh,g_WvTh); SYM(WvTl,g_WvTl);
    SYM(WrTh,g_WrTh); SYM(WrTl,g_WrTl); SYM(WoTh,g_WoTh); SYM(WoTl,g_WoTl);
    SYM(Wk2Th,g_Wk2Th); SYM(Wk2Tl,g_Wk2Tl); SYM(Wv2Th,g_Wv2Th); SYM(Wv2Tl,g_Wv2Tl);
    SYM(Wr2Th,g_Wr2Th); SYM(Wr2Tl,g_Wr2Tl);
    SYM(WdTh,g_WdTh); SYM(WdTl,g_WdTl); SYM(WoutTh,g_WoutTh); SYM(WoutTl,g_WoutTl);

    {
        TSP p{};
        p.w[0] = TSE{Win,    WinTh,  WinTl,  Hh};
        p.w[1] = TSE{Wk,     WkTh,   WkTl,   Hh};
        p.w[2] = TSE{Wv,     WvTh,   WvTl,   Hh};
        p.w[3] = TSE{Wr,     WrTh,   WrTl,   Hh};
        p.w[4] = TSE{Wo,     WoTh,   WoTl,   Hh};
        p.w[5] = TSE{Wk2,    Wk2Th,  Wk2Tl,  Hh};
        p.w[6] = TSE{Wv2,    Wv2Th,  Wv2Tl,  Hh};
        p.w[7] = TSE{Wr2,    Wr2Th,  Wr2Tl,  Hh};
        p.w[8] = TSE{Wdrift, WdTh,   WdTl,   Dd};
        p.w[9] = TSE{Wout,   WoutTh, WoutTl, Dd};
        k_transsplit<<<dim3(64, 64, 10), dim3(32, 8)>>>(p);
    }

    k_init<<<(Bsz * Hh + 255) / 256, 256>>>(enc, sc, lstate, idrift);

    const int NE = Bsz * Hh / 256;
    const dim3 thr(256);
    const dim3 thrM(NT);
    const dim3 gD(Dd / BN, Bsz / BM, 1);

    for (int s = 0; s < MAXS; s++) {
        // Win GEMM split-K x2 (256 CTAs, ~1 wave of half duration)
        { TGP p{}; p.N = Hh; p.gated = 1;
          p.z[0] = TZ{A0h, A0l, WinTh, WinTl, p_lp0, nullptr, nullptr, 0, 0, 16};
          p.z[1] = TZ{A0h, A0l, WinTh, WinTl, p_lp1, nullptr, nullptr, 0, 16, 32};
          k_mma<<<dim3(Hh/BN, Bsz/BM, 2), thrM, SMEM_TOT>>>(p); }
        k_mix<<<NE, thr>>>(b_in, mix_k, mix_v, mix_r, mix_k2, mix_r2, nullptr, 1);
        { TGP p{}; p.N = Hh; p.gated = 1;
          p.z[0] = TZ{Axkh,  Axkl,  WkTh,  WkTl,  p_k,  nullptr, nullptr, 0, 0, 32};
          p.z[1] = TZ{Axvh,  Axvl,  WvTh,  WvTl,  p_v,  nullptr, nullptr, 0, 0, 32};
          p.z[2] = TZ{Axrh,  Axrl,  WrTh,  WrTl,  p_r,  nullptr, nullptr, 2, 0, 32};
          p.z[3] = TZ{Axr2h, Axr2l, Wr2Th, Wr2Tl, p_r2, nullptr, nullptr, 2, 0, 32};
          p.z[4] = TZ{Axk2h, Axk2l, Wk2Th, Wk2Tl, nullptr, Akkh, Akkl,    3, 0, 32};
          k_mma<<<dim3(Hh/BN, Bsz/BM, 5), thrM, SMEM_TOT>>>(p); }
        k_cell<<<NE, thr>>>(tfirst, tdec, nullptr, nullptr, 1);
        { TGP p{}; p.N = Hh; p.gated = 1;
          p.z[0] = TZ{Aah,  Aal,  WoTh,  WoTl,  p_tm, nullptr, nullptr, 0, 0, 32};
          p.z[1] = TZ{Akkh, Akkl, Wv2Th, Wv2Tl, p_cm, nullptr, nullptr, 0, 0, 32};
          k_mma<<<dim3(Hh/BN, Bsz/BM, 2), thrM, SMEM_TOT>>>(p); }
        k_comb<<<NE, thr>>>(1);
        { TGP p{}; p.N = Dd; p.gated = 1;
          p.z[0] = TZ{Adh, Adl, WdTh, WdTl, p_dp0, nullptr, nullptr, 0, 0, 16};
          p.z[1] = TZ{Adh, Adl, WdTh, WdTl, p_dp1, nullptr, nullptr, 0, 16, 32};
          k_mma<<<dim3(Dd/BN, Bsz/BM, 2), thrM, SMEM_TOT>>>(p); }
        k_reduce<<<256, 256>>>(sc);
    }

    // ---- commit step (original l_state; never gated) ----
    { TGP p{}; p.N = Hh; p.gated = 0;
      p.z[0] = TZ{A0h, A0l, WinTh, WinTl, p_lp0, nullptr, nullptr, 0, 0, 16};
      p.z[1] = TZ{A0h, A0l, WinTh, WinTl, p_lp1, nullptr, nullptr, 0, 16, 32};
      k_mma<<<dim3(Hh/BN, Bsz/BM, 2), thrM, SMEM_TOT>>>(p); }
    k_mix<<<NE, thr>>>(b_in, mix_k, mix_v, mix_r, mix_k2, mix_r2, lstate, 0);
    { TGP p{}; p.N = Hh; p.gated = 0;
      p.z[0] = TZ{Axkh,  Axkl,  WkTh,  WkTl,  p_k,  nullptr, nullptr, 0, 0, 32};
      p.z[1] = TZ{Axvh,  Axvl,  WvTh,  WvTl,  p_v,  nullptr, nullptr, 0, 0, 32};
      p.z[2] = TZ{Axrh,  Axrl,  WrTh,  WrTl,  p_r,  nullptr, nullptr, 2, 0, 32};
      p.z[3] = TZ{Axr2h, Axr2l, Wr2Th, Wr2Tl, p_r2, nullptr, nullptr, 2, 0, 32};
      p.z[4] = TZ{Axk2h, Axk2l, Wk2Th, Wk2Tl, nullptr, Akkh, Akkl,    3, 0, 32};
      k_mma<<<dim3(Hh/BN, Bsz/BM, 5), thrM, SMEM_TOT>>>(p); }
    k_cell<<<NE, thr>>>(tfirst, tdec, lstate, out + OFF_NS, 0);
    { TGP p{}; p.N = Hh; p.gated = 0;
      p.z[0] = TZ{Aah,  Aal,  WoTh,  WoTl,  p_tm, nullptr, nullptr, 0, 0, 32};
      p.z[1] = TZ{Akkh, Akkl, Wv2Th, Wv2Tl, p_cm, nullptr, nullptr, 0, 0, 32};
      k_mma<<<dim3(Hh/BN, Bsz/BM, 2), thrM, SMEM_TOT>>>(p); }
    k_comb<<<NE, thr>>>(0);
    { TGP p{}; p.N = Dd; p.gated = 0; p.bias = b_out; p.enc = enc;
      p.z[0] = TZ{Adh, Adl, WoutTh, WoutTl, out + OFF_ENC, nullptr, nullptr, 5, 0, 32};
      k_mma<<<gD, thrM, SMEM_TOT>>>(p); }
    k_final<<<(Bsz * Dd + 255) / 256, 256>>>(out);
}

// round 16
// speedup vs baseline: 1.2489x; 1.0250x over previous
#include <cuda_runtime.h>
#include <cuda_fp16.h>
#include <math.h>
#include <stdint.h>

#define Bsz 512
#define Dd  1024
#define Hh  2048
#define MAXS 8

#define OFF_ENC    0
#define OFF_NS     (Bsz*Dd)
#define OFF_COMMIT (Bsz*Dd + Bsz*Hh*5)
#define OFF_DRIFT  (OFF_COMMIT + 1)

// ===================== device scratch =====================
__device__ float g_drift[Bsz*Dd];
__device__ float g_dp0[Bsz*Dd], g_dp1[Bsz*Dd], g_dp2[Bsz*Dd], g_dp3[Bsz*Dd];
__device__ float g_lp0[Bsz*Hh], g_lp1[Bsz*Hh], g_lp2[Bsz*Hh], g_lp3[Bsz*Hh];
__device__ float g_li[Bsz*Hh];
__device__ float g_k [Bsz*Hh];
__device__ float g_v [Bsz*Hh];
__device__ float g_r [Bsz*Hh];
__device__ float g_r2[Bsz*Hh];
__device__ float g_tm[Bsz*Hh], g_tm1[Bsz*Hh];
__device__ float g_cm[Bsz*Hh], g_cm1[Bsz*Hh];
__device__ float g_sxx[Bsz*Hh];
__device__ float g_saa[Bsz*Hh];
__device__ float g_sbb[Bsz*Hh];
__device__ float g_spp[Bsz*Hh];
__device__ float g_scc[Bsz*Hh];
__device__ float g_part[256][2];
__device__ float g_csum, g_cnt;
__device__ int   g_done;
__device__ int   g_rcount;

// fp16 split A buffers [512 x 2048]
__device__ __half g_A0h[Bsz*Hh],  g_A0l[Bsz*Hh];
__device__ __half g_Axkh[Bsz*Hh], g_Axkl[Bsz*Hh];
__device__ __half g_Axvh[Bsz*Hh], g_Axvl[Bsz*Hh];
__device__ __half g_Axrh[Bsz*Hh], g_Axrl[Bsz*Hh];
__device__ __half g_Axk2h[Bsz*Hh],g_Axk2l[Bsz*Hh];
__device__ __half g_Axr2h[Bsz*Hh],g_Axr2l[Bsz*Hh];
__device__ __half g_Aah[Bsz*Hh],  g_Aal[Bsz*Hh];
__device__ __half g_Akkh[Bsz*Hh], g_Akkl[Bsz*Hh];
__device__ __half g_Adh[Bsz*Hh],  g_Adl[Bsz*Hh];

// transposed + split weights [N, 2048] fp16
__device__ __half g_WinTh[Hh*2048],  g_WinTl[Hh*2048];
__device__ __half g_WkTh [Hh*Hh],    g_WkTl [Hh*Hh];
__device__ __half g_WvTh [Hh*Hh],    g_WvTl [Hh*Hh];
__device__ __half g_WrTh [Hh*Hh],    g_WrTl [Hh*Hh];
__device__ __half g_WoTh [Hh*Hh],    g_WoTl [Hh*Hh];
__device__ __half g_Wk2Th[Hh*Hh],    g_Wk2Tl[Hh*Hh];
__device__ __half g_Wv2Th[Hh*Hh],    g_Wv2Tl[Hh*Hh];
__device__ __half g_Wr2Th[Hh*Hh],    g_Wr2Tl[Hh*Hh];
__device__ __half g_WdTh [Dd*Hh],    g_WdTl [Dd*Hh];
__device__ __half g_WoutTh[Dd*Hh],   g_WoutTl[Dd*Hh];

__device__ __forceinline__ float clip50(float x){ return fminf(fmaxf(x, -50.f), 50.f); }
__device__ __forceinline__ void split_store(float v, __half* H, __half* L, size_t i){
    __half h = __float2half_rn(v);
    H[i] = h;
    L[i] = __float2half_rn(v - __half2float(h));
}
__device__ __forceinline__ void split2(float v0, float v1, __half* H, __half* L, size_t i){
    __half h0 = __float2half_rn(v0), h1 = __float2half_rn(v1);
    *(__half2*)(H + i) = __halves2half2(h0, h1);
    *(__half2*)(L + i) = __halves2half2(__float2half_rn(v0 - __half2float(h0)),
                                        __float2half_rn(v1 - __half2float(h1)));
}

// ===================== PTX primitives (compute_103-generic) =====================
__device__ __forceinline__ uint32_t smem_u32(const void* p){
    uint32_t a;
    asm("{ .reg .u64 t; cvta.to.shared.u64 t, %1; cvt.u32.u64 %0, t; }" : "=r"(a) : "l"(p));
    return a;
}
__device__ __forceinline__ void cp16(uint32_t s, const void* g){
    asm volatile("cp.async.cg.shared.global [%0], [%1], 16;" :: "r"(s), "l"(g));
}
#define CP_COMMIT() asm volatile("cp.async.commit_group;" ::: "memory")
#define CP_WAIT(n)  asm volatile("cp.async.wait_group %0;" :: "n"(n) : "memory")

__device__ __forceinline__ void ldm4(uint32_t* r, uint32_t a){
    asm volatile("ldmatrix.sync.aligned.m8n8.x4.shared.b16 {%0,%1,%2,%3}, [%4];"
        : "=r"(r[0]), "=r"(r[1]), "=r"(r[2]), "=r"(r[3]) : "r"(a));
}
__device__ __forceinline__ void mma16816(float* d, const uint32_t* a, const uint32_t* b){
    asm volatile("mma.sync.aligned.m16n8k16.row.col.f32.f16.f16.f32 "
        "{%0,%1,%2,%3}, {%4,%5,%6,%7}, {%8,%9}, {%0,%1,%2,%3};"
        : "+f"(d[0]), "+f"(d[1]), "+f"(d[2]), "+f"(d[3])
        : "r"(a[0]), "r"(a[1]), "r"(a[2]), "r"(a[3]), "r"(b[0]), "r"(b[1]));
}

// ===================== weight transpose + split (once per launch) =====================
struct TSE { const float* s; __half *dh, *dl; int nc; };
struct TSP { TSE w[10]; };

__global__ void k_transsplit(TSP p)
{
    TSE e = p.w[blockIdx.z];
    int n0 = blockIdx.y * 32;
    if (n0 >= e.nc) return;
    int k0 = blockIdx.x * 32;
    __shared__ float t[32][33];
    int tx = threadIdx.x, ty = threadIdx.y;
#pragma unroll
    for (int j = 0; j < 4; j++)
        t[ty + j*8][tx] = e.s[(size_t)(k0 + ty + j*8) * e.nc + n0 + tx];
    __syncthreads();
#pragma unroll
    for (int j = 0; j < 4; j++) {
        int n = n0 + ty + j*8, k = k0 + tx;
        float v = t[tx][ty + j*8];
        __half h = __float2half_rn(v);
        e.dh[(size_t)n * 2048 + k] = h;
        e.dl[(size_t)n * 2048 + k] = __float2half_rn(v - __half2float(h));
    }
}

// ===================== HMMA GEMM =====================
struct TZ {
    const __half *Ahi, *Alo, *Bhi, *Blo;
    float* C;
    __half *Chi, *Clo;
    int epi; // 0 plain, 2 sigmoid, 3 relu^2->split
    int tb, te;
};
struct TGP {
    TZ z[5];
    int N, gated;
};

#define BM 128
#define BN 64
#define BKh 64
#define NT 128
#define STG 2
#define APL_B 16384
#define BPL_B 8192
#define STG_BYTES (2*APL_B + 2*BPL_B)
#define SMEM_TOT (STG*STG_BYTES)

__global__ __launch_bounds__(NT, 2) void k_mma(TGP p)
{
    if (p.gated && g_done) return;
    extern __shared__ __align__(128) char sm[];
    const uint32_t smb = smem_u32(sm);
    const TZ gz = p.z[blockIdx.z];
    const int tid = threadIdx.x, l = tid & 31, wid = tid >> 5;
    const int m0 = blockIdx.y * BM, n0 = blockIdx.x * BN;
    const int wm = (wid >> 1) * 64, wn = (wid & 1) * 32;

    float acc[4][4][4];
#pragma unroll
    for (int i = 0; i < 4; i++)
#pragma unroll
        for (int j = 0; j < 4; j++)
#pragma unroll
            for (int q = 0; q < 4; q++) acc[i][j][q] = 0.f;

    int a_r[8], a_c[8]; uint32_t a_so[8];
#pragma unroll
    for (int i = 0; i < 8; i++) {
        int v = tid + i * NT;
        a_r[i] = v >> 3; a_c[i] = v & 7;
        a_so[i] = (uint32_t)(a_r[i] * 128 + ((a_c[i] ^ (a_r[i] & 7)) << 4));
    }
    int b_r[4], b_c[4]; uint32_t b_so[4];
#pragma unroll
    for (int i = 0; i < 4; i++) {
        int v = tid + i * NT;
        b_r[i] = v >> 3; b_c[i] = v & 7;
        b_so[i] = (uint32_t)(b_r[i] * 128 + ((b_c[i] ^ (b_r[i] & 7)) << 4));
    }

    auto load_stage = [&](int stage, int t){
        int kc = t * BKh;
        uint32_t base = smb + stage * STG_BYTES;
#pragma unroll
        for (int i = 0; i < 8; i++)
            cp16(base + a_so[i], gz.Ahi + (size_t)(m0 + a_r[i]) * 2048 + kc + a_c[i] * 8);
#pragma unroll
        for (int i = 0; i < 8; i++)
            cp16(base + APL_B + a_so[i], gz.Alo + (size_t)(m0 + a_r[i]) * 2048 + kc + a_c[i] * 8);
#pragma unroll
        for (int i = 0; i < 4; i++)
            cp16(base + 2*APL_B + b_so[i], gz.Bhi + (size_t)(n0 + b_r[i]) * 2048 + kc + b_c[i] * 8);
#pragma unroll
        for (int i = 0; i < 4; i++)
            cp16(base + 2*APL_B + BPL_B + b_so[i], gz.Blo + (size_t)(n0 + b_r[i]) * 2048 + kc + b_c[i] * 8);
        CP_COMMIT();
    };

    const int ar  = wm + (l & 15);
    const int ahi = (l >> 4) & 1;
    const int bn4 = wn + (l & 7) + ((l >> 4) & 1) * 8;
    const int bhi = (l >> 3) & 1;

    load_stage(gz.tb & 1, gz.tb);

    for (int t = gz.tb; t < gz.te; t++) {
        CP_WAIT(0);
        __syncthreads();
        if (t + 1 < gz.te) load_stage((t + 1) & 1, t + 1);

        uint32_t base = smb + (t & 1) * STG_BYTES;
        uint32_t Ah = base, Al = base + APL_B;
        uint32_t Bh = base + 2*APL_B, Bl = base + 2*APL_B + BPL_B;

#pragma unroll
        for (int kk = 0; kk < 4; kk++) {
            uint32_t ah[4][4], al[4][4], bh[2][4], bl[2][4];
#pragma unroll
            for (int mi = 0; mi < 4; mi++) {
                int r = ar + mi * 16, c = kk * 2 + ahi;
                uint32_t off = (uint32_t)(r * 128 + ((c ^ (r & 7)) << 4));
                ldm4(ah[mi], Ah + off);
                ldm4(al[mi], Al + off);
            }
#pragma unroll
            for (int g = 0; g < 2; g++) {
                int n = bn4 + g * 16, c = kk * 2 + bhi;
                uint32_t off = (uint32_t)(n * 128 + ((c ^ (n & 7)) << 4));
                ldm4(bh[g], Bh + off);
                ldm4(bl[g], Bl + off);
            }
#pragma unroll
            for (int mi = 0; mi < 4; mi++)
#pragma unroll
                for (int ni = 0; ni < 4; ni++)
                    mma16816(acc[mi][ni], ah[mi], &bh[ni >> 1][(ni & 1) * 2]);
#pragma unroll
            for (int mi = 0; mi < 4; mi++)
#pragma unroll
                for (int ni = 0; ni < 4; ni++)
                    mma16816(acc[mi][ni], ah[mi], &bl[ni >> 1][(ni & 1) * 2]);
#pragma unroll
            for (int mi = 0; mi < 4; mi++)
#pragma unroll
                for (int ni = 0; ni < 4; ni++)
                    mma16816(acc[mi][ni], al[mi], &bh[ni >> 1][(ni & 1) * 2]);
        }
    }

    // ---- epilogue ----
    const int rl = l >> 2, cl = (l & 3) * 2;
    const int N = p.N;
#pragma unroll
    for (int mi = 0; mi < 4; mi++) {
#pragma unroll
        for (int ni = 0; ni < 4; ni++) {
            float* a = acc[mi][ni];
#pragma unroll
            for (int h = 0; h < 2; h++) {
                int r = m0 + wm + mi * 16 + h * 8 + rl;
                int c = n0 + wn + ni * 8 + cl;
                float v0 = a[2*h], v1 = a[2*h + 1];
                size_t i0 = (size_t)r * N + c;

                if (gz.epi == 3) {
                    float t0 = fmaxf(v0, 0.f); v0 = t0 * t0;
                    float t1 = fmaxf(v1, 0.f); v1 = t1 * t1;
                    split2(v0, v1, gz.Chi, gz.Clo, i0);
                } else {
                    if (gz.epi == 2) {
                        v0 = 1.f / (1.f + expf(-v0));
                        v1 = 1.f / (1.f + expf(-v1));
                    }
                    *(float2*)(gz.C + i0) = make_float2(v0, v1);
                }
            }
        }
    }
}

// ===================== elementwise kernels =====================
__global__ void k_init(const float* enc, const float* sc,
                       const float* lstate, const float* idrift)
{
    int i = blockIdx.x * blockDim.x + threadIdx.x;
    if (i < Bsz * Hh) {
        const float* s = lstate + (size_t)i * 5;
        g_sxx[i] = s[0]; g_saa[i] = s[1]; g_sbb[i] = s[2]; g_spp[i] = s[3]; g_scc[i] = s[4];
    }
    if (i < Bsz * Dd) {
        g_drift[i] = idrift[i];
        int m = i >> 10, col = i & 1023;
        size_t a0 = (size_t)m * 2048 + col;
        split_store(enc[i], g_A0h, g_A0l, a0);
        split_store(sc[i] + idrift[i], g_A0h, g_A0l, a0 + 1024);
    }
    if (i == 0) { g_csum = 0.f; g_cnt = 0.f; g_done = 0; g_rcount = 0; }
}

// combine 4 split-K li partials + bias + clip, then 5 mixed split operands
__global__ void k_mix(const float* bias,
                      const float* mk, const float* mv, const float* mr,
                      const float* mk2, const float* mr2,
                      const float* lstate, int gated)
{
    if (gated && g_done) return;
    int i = blockIdx.x * blockDim.x + threadIdx.x;
    int h = i & (Hh - 1);
    float li = clip50(g_lp0[i] + g_lp1[i] + g_lp2[i] + g_lp3[i] + bias[h]);
    g_li[i] = li;
    float xx, cc;
    if (lstate) { xx = lstate[(size_t)i*5 + 0]; cc = lstate[(size_t)i*5 + 4]; }
    else        { xx = g_sxx[i];                cc = g_scc[i]; }
    float a;
    a = mk[h];  split_store(li*a + xx*(1.f-a), g_Axkh,  g_Axkl,  i);
    a = mv[h];  split_store(li*a + xx*(1.f-a), g_Axvh,  g_Axvl,  i);
    a = mr[h];  split_store(li*a + xx*(1.f-a), g_Axrh,  g_Axrl,  i);
    a = mk2[h]; split_store(li*a + cc*(1.f-a), g_Axk2h, g_Axk2l, i);
    a = mr2[h]; split_store(li*a + cc*(1.f-a), g_Axr2h, g_Axr2l, i);
}

__global__ void k_cell(const float* tf, const float* td,
                       const float* lstate_in, float* ns_out, int gated)
{
    if (gated && g_done) return;
    int i = blockIdx.x * blockDim.x + threadIdx.x;
    int h = i & (Hh - 1);
    float kx = g_k[i], v = g_v[i], r = g_r[i], li = g_li[i];
    float aa, bb, pp;
    if (lstate_in) {
        const float* s = lstate_in + (size_t)i * 5;
        aa = s[1]; bb = s[2]; pp = s[3];
    } else {
        aa = g_saa[i]; bb = g_sbb[i]; pp = g_spp[i];
    }
    float ww = tf[h] + kx;
    float q  = fmaxf(pp, ww);
    float e1 = expf(pp - q), e2 = expf(ww - q);
    float wkv = (e1 * aa + e2 * v) / (e1 * bb + e2);
    split_store(r * wkv, g_Aah, g_Aal, i);

    float ww2 = pp - expf(td[h]);
    float q2  = fmaxf(ww2, kx);
    float e1b = expf(ww2 - q2), e2b = expf(kx - q2);
    float naa = clip50(e1b * aa + e2b * v);
    float nbb = clip50(e1b * bb + e2b);
    float npp = clip50(q2);
    float nxx = clip50(li);
    if (ns_out) {
        float* o = ns_out + (size_t)i * 5;
        o[0] = nxx; o[1] = naa; o[2] = nbb; o[3] = npp; o[4] = nxx;
    } else {
        g_sxx[i] = nxx; g_saa[i] = naa; g_sbb[i] = nbb; g_spp[i] = npp; g_scc[i] = nxx;
    }
}

// combine tm/cm split-K partials, form drift-GEMM operand
__global__ void k_comb(int gated)
{
    if (gated && g_done) return;
    int i = blockIdx.x * blockDim.x + threadIdx.x;
    float v = (g_tm[i] + g_tm1[i]) + g_r2[i] * (g_cm[i] + g_cm1[i]);
    split_store(v, g_Adh, g_Adl, i);
}

// drift update (4 split-K partials + tanh) + A0 refresh + partials + fused final reduce
__global__ void k_reduce(const float* sc)
{
    if (g_done) return;
    __shared__ float sA[256], sB[256];
    __shared__ int isLast;
    int t = threadIdx.x;
    size_t base = (size_t)blockIdx.x * 2048 + t;
    float sa = 0.f, sn = 0.f;
#pragma unroll
    for (int j = 0; j < 8; j++) {
        size_t i = base + (size_t)j * 256;
        float d  = tanhf(g_dp0[i] + g_dp1[i] + g_dp2[i] + g_dp3[i]);
        float nd = fminf(fmaxf(g_drift[i] + d, -5.f), 5.f);
        g_drift[i] = nd;
        int m = (int)(i >> 10), col = (int)(i & 1023);
        split_store(sc[i] + nd, g_A0h, g_A0l, (size_t)m * 2048 + 1024 + col);
        sa += fabsf(d);
        sn += nd * nd;
    }
    sA[t] = sa; sB[t] = sn;
    __syncthreads();
    for (int s = 128; s > 0; s >>= 1) {
        if (t < s) { sA[t] += sA[t + s]; sB[t] += sB[t + s]; }
        __syncthreads();
    }
    if (t == 0) {
        g_part[blockIdx.x][0] = sA[0];
        g_part[blockIdx.x][1] = sB[0];
        __threadfence();
        int c = atomicAdd(&g_rcount, 1);
        isLast = (c == 255);
    }
    __syncthreads();
    if (!isLast) return;

    sA[t] = g_part[t][0]; sB[t] = g_part[t][1];
    __syncthreads();
    for (int s = 128; s > 0; s >>= 1) {
        if (t < s) { sA[t] += sA[t + s]; sB[t] += sB[t + s]; }
        __syncthreads();
    }
    if (t == 0) {
        float hinge = fminf(fmaxf(sB[0] / (float)Bsz - 0.1f, 0.f), 100.f);
        g_csum += hinge;
        g_cnt  += 1.f;
        if (sA[0] * (1.f / (float)(Bsz * Dd)) < 0.01f) g_done = 1;
        g_rcount = 0;
    }
}

// final: enc-out from 4 Wout partials + bias, drift, commitment
__global__ void k_final(const float* enc, const float* b_out, float* out)
{
    int i = blockIdx.x * blockDim.x + threadIdx.x;
    if (i < Bsz * Dd) {
        int col = i & 1023;
        out[OFF_ENC + i] = enc[i] + (g_dp0[i] + g_dp1[i] + g_dp2[i] + g_dp3[i]) + b_out[col];
        out[OFF_DRIFT + i] = g_drift[i];
    }
    if (i == 0) out[OFF_COMMIT] = g_csum / fmaxf(g_cnt, 1.f);
}

// ===================== host =====================
#define SYM(p, s) cudaGetSymbolAddress((void**)&(p), s)

extern "C" void kernel_launch(void* const* d_in, const int* in_sizes, int n_in,
                              void* d_out, int out_size)
{
    (void)in_sizes; (void)n_in; (void)out_size;
    const float* enc    = (const float*)d_in[0];
    const float* sc     = (const float*)d_in[1];
    const float* lstate = (const float*)d_in[2];
    const float* idrift = (const float*)d_in[3];
    const float* Win    = (const float*)d_in[4];
    const float* b_in   = (const float*)d_in[5];
    const float* Wdrift = (const float*)d_in[6];
    const float* Wout   = (const float*)d_in[7];
    const float* b_out  = (const float*)d_in[8];
    const float* mix_k  = (const float*)d_in[9];
    const float* mix_v  = (const float*)d_in[10];
    const float* mix_r  = (const float*)d_in[11];
    const float* mix_k2 = (const float*)d_in[12];
    const float* mix_r2 = (const float*)d_in[13];
    const float* tdec   = (const float*)d_in[14];
    const float* tfirst = (const float*)d_in[15];
    const float* Wk  = (const float*)d_in[16];
    const float* Wv  = (const float*)d_in[17];
    const float* Wr  = (const float*)d_in[18];
    const float* Wo  = (const float*)d_in[19];
    const float* Wk2 = (const float*)d_in[20];
    const float* Wv2 = (const float*)d_in[21];
    const float* Wr2 = (const float*)d_in[22];
    float* out = (float*)d_out;

    cudaFuncSetAttribute(k_mma, cudaFuncAttributeMaxDynamicSharedMemorySize, SMEM_TOT);

    float *p_k, *p_v, *p_r, *p_r2, *p_tm, *p_tm1, *p_cm, *p_cm1;
    float *p_dp0, *p_dp1, *p_dp2, *p_dp3, *p_lp0, *p_lp1, *p_lp2, *p_lp3;
    SYM(p_k, g_k); SYM(p_v, g_v); SYM(p_r, g_r); SYM(p_r2, g_r2);
    SYM(p_tm, g_tm); SYM(p_tm1, g_tm1); SYM(p_cm, g_cm); SYM(p_cm1, g_cm1);
    SYM(p_dp0, g_dp0); SYM(p_dp1, g_dp1); SYM(p_dp2, g_dp2); SYM(p_dp3, g_dp3);
    SYM(p_lp0, g_lp0); SYM(p_lp1, g_lp1); SYM(p_lp2, g_lp2); SYM(p_lp3, g_lp3);

    __half *A0h,*A0l,*Axkh,*Axkl,*Axvh,*Axvl,*Axrh,*Axrl,*Axk2h,*Axk2l,*Axr2h,*Axr2l;
    __half *Aah,*Aal,*Akkh,*Akkl,*Adh,*Adl;
    SYM(A0h,g_A0h); SYM(A0l,g_A0l);
    SYM(Axkh,g_Axkh); SYM(Axkl,g_Axkl); SYM(Axvh,g_Axvh); SYM(Axvl,g_Axvl);
    SYM(Axrh,g_Axrh); SYM(Axrl,g_Axrl); SYM(Axk2h,g_Axk2h); SYM(Axk2l,g_Axk2l);
    SYM(Axr2h,g_Axr2h); SYM(Axr2l,g_Axr2l);
    SYM(Aah,g_Aah); SYM(Aal,g_Aal); SYM(Akkh,g_Akkh); SYM(Akkl,g_Akkl);
    SYM(Adh,g_Adh); SYM(Adl,g_Adl);

    __half *WinTh,*WinTl,*WkTh,*WkTl,*WvTh,*WvTl,*WrTh,*WrTl,*WoTh,*WoTl;
    __half *Wk2Th,*Wk2Tl,*Wv2Th,*Wv2Tl,*Wr2Th,*Wr2Tl,*WdTh,*WdTl,*WoutTh,*WoutTl;
    SYM(WinTh,g_WinTh); SYM(WinTl,g_WinTl);
    SYM(WkTh,g_WkTh); SYM(WkTl,g_WkTl); SYM(WvTh,g_WvTh); SYM(WvTl,g_WvTl);
    SYM(WrTh,g_WrTh); SYM(WrTl,g_WrTl); SYM(WoTh,g_WoTh); SYM(WoTl,g_WoTl);
    SYM(Wk2Th,g_Wk2Th); SYM(Wk2Tl,g_Wk2Tl); SYM(Wv2Th,g_Wv2Th); SYM(Wv2Tl,g_Wv2Tl);
    SYM(Wr2Th,g_Wr2Th); SYM(Wr2Tl,g_Wr2Tl);
    SYM(WdTh,g_WdTh); SYM(WdTl,g_WdTl); SYM(WoutTh,g_WoutTh); SYM(WoutTl,g_WoutTl);

    {
        TSP p{};
        p.w[0] = TSE{Win,    WinTh,  WinTl,  Hh};
        p.w[1] = TSE{Wk,     WkTh,   WkTl,   Hh};
        p.w[2] = TSE{Wv,     WvTh,   WvTl,   Hh};
        p.w[3] = TSE{Wr,     WrTh,   WrTl,   Hh};
        p.w[4] = TSE{Wo,     WoTh,   WoTl,   Hh};
        p.w[5] = TSE{Wk2,    Wk2Th,  Wk2Tl,  Hh};
        p.w[6] = TSE{Wv2,    Wv2Th,  Wv2Tl,  Hh};
        p.w[7] = TSE{Wr2,    Wr2Th,  Wr2Tl,  Hh};
        p.w[8] = TSE{Wdrift, WdTh,   WdTl,   Dd};
        p.w[9] = TSE{Wout,   WoutTh, WoutTl, Dd};
        k_transsplit<<<dim3(64, 64, 10), dim3(32, 8)>>>(p);
    }

    k_init<<<(Bsz * Hh + 255) / 256, 256>>>(enc, sc, lstate, idrift);

    const int NE = Bsz * Hh / 256;
    const dim3 thr(256);
    const dim3 thrM(NT);

    auto step_body = [&](int gated, const float* lst_mix){
        // Win GEMM split-K x4 (512 quarter-K CTAs)
        { TGP p{}; p.N = Hh; p.gated = gated;
          p.z[0] = TZ{A0h, A0l, WinTh, WinTl, p_lp0, nullptr, nullptr, 0, 0, 8};
          p.z[1] = TZ{A0h, A0l, WinTh, WinTl, p_lp1, nullptr, nullptr, 0, 8, 16};
          p.z[2] = TZ{A0h, A0l, WinTh, WinTl, p_lp2, nullptr, nullptr, 0, 16, 24};
          p.z[3] = TZ{A0h, A0l, WinTh, WinTl, p_lp3, nullptr, nullptr, 0, 24, 32};
          k_mma<<<dim3(Hh/BN, Bsz/BM, 4), thrM, SMEM_TOT>>>(p); }
        k_mix<<<NE, thr>>>(b_in, mix_k, mix_v, mix_r, mix_k2, mix_r2, lst_mix, gated);
        // 5-way batch (full-K; already >2 waves, packs well)
        { TGP p{}; p.N = Hh; p.gated = gated;
          p.z[0] = TZ{Axkh,  Axkl,  WkTh,  WkTl,  p_k,  nullptr, nullptr, 0, 0, 32};
          p.z[1] = TZ{Axvh,  Axvl,  WvTh,  WvTl,  p_v,  nullptr, nullptr, 0, 0, 32};
          p.z[2] = TZ{Axrh,  Axrl,  WrTh,  WrTl,  p_r,  nullptr, nullptr, 2, 0, 32};
          p.z[3] = TZ{Axr2h, Axr2l, Wr2Th, Wr2Tl, p_r2, nullptr, nullptr, 2, 0, 32};
          p.z[4] = TZ{Axk2h, Axk2l, Wk2Th, Wk2Tl, nullptr, Akkh, Akkl,    3, 0, 32};
          k_mma<<<dim3(Hh/BN, Bsz/BM, 5), thrM, SMEM_TOT>>>(p); }
    };

    for (int s = 0; s < MAXS; s++) {
        step_body(1, nullptr);
        k_cell<<<NE, thr>>>(tfirst, tdec, nullptr, nullptr, 1);
        // Wo/Wv2 GEMMs split-K x2 (512 half-K CTAs)
        { TGP p{}; p.N = Hh; p.gated = 1;
          p.z[0] = TZ{Aah,  Aal,  WoTh,  WoTl,  p_tm,  nullptr, nullptr, 0, 0, 16};
          p.z[1] = TZ{Aah,  Aal,  WoTh,  WoTl,  p_tm1, nullptr, nullptr, 0, 16, 32};
          p.z[2] = TZ{Akkh, Akkl, Wv2Th, Wv2Tl, p_cm,  nullptr, nullptr, 0, 0, 16};
          p.z[3] = TZ{Akkh, Akkl, Wv2Th, Wv2Tl, p_cm1, nullptr, nullptr, 0, 16, 32};
          k_mma<<<dim3(Hh/BN, Bsz/BM, 4), thrM, SMEM_TOT>>>(p); }
        k_comb<<<NE, thr>>>(1);
        // drift GEMM split-K x4 (256 quarter-K CTAs)
        { TGP p{}; p.N = Dd; p.gated = 1;
          p.z[0] = TZ{Adh, Adl, WdTh, WdTl, p_dp0, nullptr, nullptr, 0, 0, 8};
          p.z[1] = TZ{Adh, Adl, WdTh, WdTl, p_dp1, nullptr, nullptr, 0, 8, 16};
          p.z[2] = TZ{Adh, Adl, WdTh, WdTl, p_dp2, nullptr, nullptr, 0, 16, 24};
          p.z[3] = TZ{Adh, Adl, WdTh, WdTl, p_dp3, nullptr, nullptr, 0, 24, 32};
          k_mma<<<dim3(Dd/BN, Bsz/BM, 4), thrM, SMEM_TOT>>>(p); }
        k_reduce<<<256, 256>>>(sc);
    }

    // ---- commit step (original l_state; never gated) ----
    step_body(0, lstate);
    k_cell<<<NE, thr>>>(tfirst, tdec, lstate, out + OFF_NS, 0);
    { TGP p{}; p.N = Hh; p.gated = 0;
      p.z[0] = TZ{Aah,  Aal,  WoTh,  WoTl,  p_tm,  nullptr, nullptr, 0, 0, 16};
      p.z[1] = TZ{Aah,  Aal,  WoTh,  WoTl,  p_tm1, nullptr, nullptr, 0, 16, 32};
      p.z[2] = TZ{Akkh, Akkl, Wv2Th, Wv2Tl, p_cm,  nullptr, nullptr, 0, 0, 16};
      p.z[3] = TZ{Akkh, Akkl, Wv2Th, Wv2Tl, p_cm1, nullptr, nullptr, 0, 16, 32};
      k_mma<<<dim3(Hh/BN, Bsz/BM, 4), thrM, SMEM_TOT>>>(p); }
    k_comb<<<NE, thr>>>(0);
    // final Wout GEMM split-K x4 into dp0..3; epilogue fused into k_final
    { TGP p{}; p.N = Dd; p.gated = 0;
      p.z[0] = TZ{Adh, Adl, WoutTh, WoutTl, p_dp0, nullptr, nullptr, 0, 0, 8};
      p.z[1] = TZ{Adh, Adl, WoutTh, WoutTl, p_dp1, nullptr, nullptr, 0, 8, 16};
      p.z[2] = TZ{Adh, Adl, WoutTh, WoutTl, p_dp2, nullptr, nullptr, 0, 16, 24};
      p.z[3] = TZ{Adh, Adl, WoutTh, WoutTl, p_dp3, nullptr, nullptr, 0, 24, 32};
      k_mma<<<dim3(Dd/BN, Bsz/BM, 4), thrM, SMEM_TOT>>>(p); }
    k_final<<<(Bsz * Dd + 255) / 256, 256>>>(enc, b_out, out);
}